// round 2
// baseline (speedup 1.0000x reference)
#include <cuda_runtime.h>
#include <math.h>
#include <stdint.h>

// Problem constants
#define BB   2
#define LL   2048
#define HH   16
#define DD   64
#define HIDN 1024
#define NROWS (BB*LL*HH)     // 65536 gate rows
#define NBL   (BB*LL)        // 4096 (b,l) positions

// Scratch (static device globals — no allocation)
__device__ float g_wsum[12 * 128];          // column sums of W1 stat blocks
__device__ float g_hidpart[NBL * 128];      // hidden @ W1[0:1024] + b1

// ---- packed fp32x2 helpers ----
__device__ __forceinline__ void ffma2(unsigned long long& d,
                                      unsigned long long a,
                                      unsigned long long b) {
    asm("fma.rn.f32x2 %0, %1, %2, %0;" : "+l"(d) : "l"(a), "l"(b));
}
__device__ __forceinline__ unsigned long long pack2(float x, float y) {
    unsigned long long r;
    asm("mov.b64 %0, {%1, %2};" : "=l"(r) : "f"(x), "f"(y));
    return r;
}
__device__ __forceinline__ float2 unpack2(unsigned long long v) {
    float2 f;
    asm("mov.b64 {%0, %1}, %2;" : "=f"(f.x), "=f"(f.y) : "l"(v));
    return f;
}

// ============================================================================
// Pre-kernel: hidden GEMM (blocks 0..127) + wsum (blocks 128..139), one launch
// hid: g_hidpart[m][j] = sum_k hidden[m][k]*W1[k][j] + b1[j]
//      M=4096 K=1024 N=128; N split in halves -> 128 blocks fill the chip.
// ============================================================================
__global__ __launch_bounds__(512) void pre_kernel(
    const float* __restrict__ hidden,
    const float* __restrict__ W1,
    const float* __restrict__ b1)
{
    if (blockIdx.x >= 128) {
        // ---- wsum: column sums of the 12 stat blocks of W1 (rows 1024..1791)
        int ps = blockIdx.x - 128;
        if (threadIdx.x < 128) {
            int j = threadIdx.x;
            int base = 1024 + ps * 64;
            float s = 0.f;
#pragma unroll
            for (int d = 0; d < 64; d++) s += W1[(base + d) * 128 + j];
            g_wsum[ps * 128 + j] = s;
        }
        return;
    }

    __shared__ float A_T[32 * 66];    // [k][row], pitch 66 (LDS.64-aligned, low conflict)
    __shared__ float B_s[32 * 64];    // [k][col] this block's 64-col half

    int tid = threadIdx.x;
    int l = tid & 31;                  // row pair: rows 2l, 2l+1 within tile
    int g = tid >> 5;                  // col group: 4 cols c0+4g..+3
    int m0 = (blockIdx.x >> 1) * 64;
    int c0 = (blockIdx.x & 1) * 64;

    unsigned long long acc[2][2];
    acc[0][0] = acc[0][1] = acc[1][0] = acc[1][1] = 0ull;

    for (int k0 = 0; k0 < HIDN; k0 += 32) {
        for (int i = tid; i < 64 * 32; i += 512) {
            int r = i >> 5, kk = i & 31;
            A_T[kk * 66 + r] = hidden[(size_t)(m0 + r) * HIDN + k0 + kk];
        }
        for (int i = tid; i < 32 * 64; i += 512) {
            int kk = i >> 6, c = i & 63;
            B_s[kk * 64 + c] = W1[(k0 + kk) * 128 + c0 + c];
        }
        __syncthreads();
#pragma unroll 8
        for (int kk = 0; kk < 32; kk++) {
            ulonglong2 wv = *(const ulonglong2*)&B_s[kk * 64 + 4 * g]; // 4 cols = 2 f32x2
            float2 xv = *(const float2*)&A_T[kk * 66 + 2 * l];
            unsigned long long x0 = pack2(xv.x, xv.x);
            unsigned long long x1 = pack2(xv.y, xv.y);
            ffma2(acc[0][0], x0, wv.x); ffma2(acc[0][1], x0, wv.y);
            ffma2(acc[1][0], x1, wv.x); ffma2(acc[1][1], x1, wv.y);
        }
        __syncthreads();
    }
    float4 bv = *(const float4*)&b1[c0 + 4 * g];
#pragma unroll
    for (int e = 0; e < 2; e++) {
        float2 a0 = unpack2(acc[e][0]), a1 = unpack2(acc[e][1]);
        float4 v = make_float4(a0.x + bv.x, a0.y + bv.y, a1.x + bv.z, a1.y + bv.w);
        *(float4*)&g_hidpart[(size_t)(m0 + 2 * l + e) * 128 + c0 + 4 * g] = v;
    }
}

// ============================================================================
// Main kernel: persistent CTAs, resident 256x128 branch-W in smem.
// Tile TM=64 rows. 512 threads: lane l -> rows {2l,2l+1}, group g -> cols 8g..8g+7.
// ============================================================================
#define TM 64

struct SmemMain {
    float W[256 * 128];      // 131072 B  branch weight block (W1 rows 1792..2047)
    float xT[256 * 66];      //  67584 B  transposed branch tile [k][row], pitch 66
    float wsum[12 * 128];    //   6144 B
    float stat[12 * 66];     //   3168 B  [ps][row], pitch 66
    float w2[128 * 4];       //   2048 B
};                            // 210016 B total

__global__ __launch_bounds__(512, 1) void main_kernel(
    const float* __restrict__ br0, const float* __restrict__ br1,
    const float* __restrict__ br2, const float* __restrict__ br3,
    const float* __restrict__ W1, const float* __restrict__ W2,
    const float* __restrict__ b2, const float* __restrict__ eps_floor,
    const float* __restrict__ temp, float* __restrict__ out)
{
    extern __shared__ float smem_raw[];
    SmemMain* S = (SmemMain*)smem_raw;
    float* red = S->xT;    // epilogue partials alias xT: [g][r*4+n], pitch 260
    int tid = threadIdx.x;
    int l = tid & 31;      // row lane
    int g = tid >> 5;      // col group (0..15), cols 8g..8g+7

    // One-time loads
    {
        const float4* Wb = (const float4*)(W1 + 1792 * 128);
        for (int i = tid; i < 256 * 128 / 4; i += 512) ((float4*)S->W)[i] = Wb[i];
        for (int i = tid; i < 12 * 128; i += 512) S->wsum[i] = g_wsum[i];
        for (int i = tid; i < 512; i += 512) S->w2[i] = W2[i];
    }

    const int ntiles = NROWS / TM;   // 1024
    for (int tile = blockIdx.x; tile < ntiles; tile += gridDim.x) {
        int rg0 = tile * TM;
        __syncthreads();   // covers one-time loads (iter 0) and red/stat reuse

        // ---- load branch tile transposed: xT[p*64+d][r] = branch_p[rg0+r][d] ----
        {
#pragma unroll
            for (int p = 0; p < 4; p++) {
                const float* bp = (p == 0) ? br0 : (p == 1) ? br1 : (p == 2) ? br2 : br3;
                const float4* bp4 = (const float4*)(bp + (size_t)rg0 * 64);
                for (int i = tid; i < 64 * 16; i += 512) {   // 1024 float4
                    int r = i >> 4, d4 = (i & 15) * 4;
                    float4 v = bp4[i];
                    int kb = (p * 64 + d4) * 66 + r;
                    S->xT[kb]          = v.x;
                    S->xT[kb + 66]     = v.y;
                    S->xT[kb + 132]    = v.z;
                    S->xT[kb + 198]    = v.w;
                }
            }
        }
        __syncthreads();

        // ---- stats: one thread per (row, branch), write stat[ps][r] ----
        if (tid < 256) {
            int r = tid & 63, p = tid >> 6;
            const float* xr = &S->xT[(p * 64) * 66 + r];
            float sum = 0.f, sq = 0.f, mx = -INFINITY;
#pragma unroll 8
            for (int d = 0; d < 64; d++) {
                float v = xr[d * 66];
                sum += v; sq += v * v; mx = fmaxf(mx, v);
            }
            float mean = sum * (1.0f / 64.0f);
            float rms = sqrtf(fmaxf(sq * (1.0f / 64.0f), 1e-8f));
            S->stat[(p * 3 + 0) * 66 + r] = mean;
            S->stat[(p * 3 + 1) * 66 + r] = rms;
            S->stat[(p * 3 + 2) * 66 + r] = mx;
        }
        // (no sync needed: GEMM reads only xT; stats consumed after post-GEMM sync)

        // ---- branch GEMM: rows {2l,2l+1} x cols 8g..8g+7, f32x2 ----
        unsigned long long acc[2][4];
#pragma unroll
        for (int c = 0; c < 4; c++) { acc[0][c] = 0ull; acc[1][c] = 0ull; }
        {
            const float* xb = &S->xT[2 * l];
            const float* wb = &S->W[8 * g];
#pragma unroll 4
            for (int k = 0; k < 256; k++) {
                ulonglong2 wv01 = *(const ulonglong2*)(wb + k * 128);      // cols 8g..+3
                ulonglong2 wv23 = *(const ulonglong2*)(wb + k * 128 + 4);  // cols +4..+7
                float2 xv = *(const float2*)(xb + k * 66);
                unsigned long long x0 = pack2(xv.x, xv.x);
                unsigned long long x1 = pack2(xv.y, xv.y);
                ffma2(acc[0][0], x0, wv01.x); ffma2(acc[0][1], x0, wv01.y);
                ffma2(acc[0][2], x0, wv23.x); ffma2(acc[0][3], x0, wv23.y);
                ffma2(acc[1][0], x1, wv01.x); ffma2(acc[1][1], x1, wv01.y);
                ffma2(acc[1][2], x1, wv23.x); ffma2(acc[1][3], x1, wv23.y);
            }
        }
        __syncthreads();   // all xT reads done -> red may overwrite; stats visible

        // ---- epilogue: hid + stats, GELU, per-group W2 partials -> red ----
#pragma unroll
        for (int e = 0; e < 2; e++) {
            int r = 2 * l + e;
            int rg = rg0 + r;
            float h[8];
#pragma unroll
            for (int c = 0; c < 4; c++) {
                float2 t2 = unpack2(acc[e][c]);
                h[2 * c] = t2.x; h[2 * c + 1] = t2.y;
            }
            const float* hp = &g_hidpart[(size_t)(rg >> 4) * 128 + 8 * g];
            float4 hA = *(const float4*)hp;
            float4 hB = *(const float4*)(hp + 4);
            h[0] += hA.x; h[1] += hA.y; h[2] += hA.z; h[3] += hA.w;
            h[4] += hB.x; h[5] += hB.y; h[6] += hB.z; h[7] += hB.w;
#pragma unroll
            for (int ps = 0; ps < 12; ps++) {
                float sv = S->stat[ps * 66 + r];
                float4 wA = *(const float4*)&S->wsum[ps * 128 + 8 * g];
                float4 wB = *(const float4*)&S->wsum[ps * 128 + 8 * g + 4];
                h[0] += sv * wA.x; h[1] += sv * wA.y; h[2] += sv * wA.z; h[3] += sv * wA.w;
                h[4] += sv * wB.x; h[5] += sv * wB.y; h[6] += sv * wB.z; h[7] += sv * wB.w;
            }
            float lp0 = 0.f, lp1 = 0.f, lp2 = 0.f, lp3 = 0.f;
#pragma unroll
            for (int c = 0; c < 8; c++) {
                float gv = 0.5f * h[c] * (1.0f + erff(h[c] * 0.7071067811865476f));
                float4 w2v = *(const float4*)&S->w2[(8 * g + c) * 4];
                lp0 += gv * w2v.x; lp1 += gv * w2v.y;
                lp2 += gv * w2v.z; lp3 += gv * w2v.w;
            }
            *(float4*)&red[g * 260 + r * 4] = make_float4(lp0, lp1, lp2, lp3);
        }
        __syncthreads();

        // ---- reduce 16 groups, softmax over 4-lane groups, store ----
        if (tid < 256) {
            int r = tid >> 2, n = tid & 3;
            float s = 0.f;
#pragma unroll
            for (int gg = 0; gg < 16; gg++) s += red[gg * 260 + r * 4 + n];
            int rg = rg0 + r;
            int hh = rg & (HH - 1);
            float t = fminf(fmaxf(temp[hh], 0.2f), 10.0f);
            float q = (s + b2[n]) / t;
            float m = q;
            m = fmaxf(m, __shfl_xor_sync(0xffffffffu, m, 1));
            m = fmaxf(m, __shfl_xor_sync(0xffffffffu, m, 2));
            float ev = expf(q - m);
            float se = ev;
            se += __shfl_xor_sync(0xffffffffu, se, 1);
            se += __shfl_xor_sync(0xffffffffu, se, 2);
            float w = ev / se;
            float fl = fminf(fmaxf(eps_floor[hh * 4 + n], 1e-7f), 0.1f);
            w = fmaxf(w, fl);
            float sw = w;
            sw += __shfl_xor_sync(0xffffffffu, sw, 1);
            sw += __shfl_xor_sync(0xffffffffu, sw, 2);
            out[(size_t)rg * 4 + n] = w / sw;
        }
    }
}

// ============================================================================
// Launch
// ============================================================================
extern "C" void kernel_launch(void* const* d_in, const int* in_sizes, int n_in,
                              void* d_out, int out_size)
{
    const float* hidden = (const float*)d_in[0];
    const float* br0    = (const float*)d_in[1];
    const float* br1    = (const float*)d_in[2];
    const float* br2    = (const float*)d_in[3];
    const float* br3    = (const float*)d_in[4];
    const float* W1     = (const float*)d_in[5];
    const float* b1     = (const float*)d_in[6];
    const float* W2     = (const float*)d_in[7];
    const float* b2     = (const float*)d_in[8];
    const float* eps    = (const float*)d_in[9];
    const float* temp   = (const float*)d_in[10];
    float* out = (float*)d_out;

    int sms = 148;
    cudaDeviceGetAttribute(&sms, cudaDevAttrMultiProcessorCount, 0);

    cudaFuncSetAttribute(main_kernel, cudaFuncAttributeMaxDynamicSharedMemorySize,
                         (int)sizeof(SmemMain));

    pre_kernel<<<140, 512>>>(hidden, W1, b1);
    main_kernel<<<sms, 512, sizeof(SmemMain)>>>(br0, br1, br2, br3, W1, W2,
                                                b2, eps, temp, out);
}

// round 6
// speedup vs baseline: 1.3240x; 1.3240x over previous
#include <cuda_runtime.h>
#include <math.h>
#include <stdint.h>

#define HH    16
#define NROWS 65536
#define NBL   4096

__device__ float g_wsum[12 * 128];
__device__ float g_hidpart[NBL * 128];   // hidden @ W1[0:1024]  (b1 added here)

// ---- packed fp32x2 helpers ----
__device__ __forceinline__ void ffma2(unsigned long long& d,
                                      unsigned long long a,
                                      unsigned long long b) {
    asm("fma.rn.f32x2 %0, %1, %2, %0;" : "+l"(d) : "l"(a), "l"(b));
}
__device__ __forceinline__ unsigned long long pack2s(float x) {
    unsigned long long r;
    asm("mov.b64 %0, {%1, %1};" : "=l"(r) : "f"(x));
    return r;
}
__device__ __forceinline__ float2 unpack2(unsigned long long v) {
    float2 f;
    asm("mov.b64 {%0, %1}, %2;" : "=f"(f.x), "=f"(f.y) : "l"(v));
    return f;
}

// ============================================================================
// Pre-kernel: blocks 0..255 = hidden GEMM (Mtile 32 x Ntile 64, k-split 2)
//             blocks 256..267 = wsum
// ============================================================================
#define PRE_A_HALF (32 * 68)     // 2176 floats per half
#define PRE_B_HALF (64 * 64)     // 4096 floats per half
#define PRE_SMEM_FLOATS (2 * PRE_A_HALF + 2 * PRE_B_HALF)   // 12544 -> 50176 B

__global__ __launch_bounds__(256) void pre_kernel(
    const float* __restrict__ hidden,
    const float* __restrict__ W1,
    const float* __restrict__ b1)
{
    if (blockIdx.x >= 256) {
        int ps = blockIdx.x - 256;
        if (threadIdx.x < 128) {
            int j = threadIdx.x;
            int base = 1024 + ps * 64;
            float s = 0.f;
#pragma unroll
            for (int d = 0; d < 64; d++) s += W1[(base + d) * 128 + j];
            g_wsum[ps * 128 + j] = s;
        }
        return;
    }

    extern __shared__ float sm[];
    float* As = sm;                       // [2][32][68]
    float* Bs = sm + 2 * PRE_A_HALF;      // [2][64][64]
    float* pbuf = sm;                     // alias (reduce buffer, 32x66)

    int tid = threadIdx.x;
    int l = tid & 31, w = tid >> 5;
    int kh = w >> 2, wr = w & 3;
    int rowg = l >> 3, colg = l & 7;
    int m0 = (blockIdx.x >> 1) * 32;
    int c0 = (blockIdx.x & 1) * 64;

    unsigned long long acc[2][2][2];      // [j row][q quad][pair]
#pragma unroll
    for (int j = 0; j < 2; j++)
#pragma unroll
        for (int q = 0; q < 2; q++) { acc[j][q][0] = 0ull; acc[j][q][1] = 0ull; }

    for (int t = 0; t < 8; t++) {
        __syncthreads();
#pragma unroll
        for (int h = 0; h < 2; h++) {
            int kbase = h * 512 + t * 64;
#pragma unroll
            for (int it = 0; it < 2; it++) {       // A: 512 float4
                int idx = tid + it * 256;
                int r = idx >> 4, k4 = (idx & 15) * 4;
                *(float4*)&As[h * PRE_A_HALF + r * 68 + k4] =
                    *(const float4*)&hidden[(size_t)(m0 + r) * 1024 + kbase + k4];
            }
#pragma unroll
            for (int it = 0; it < 4; it++) {       // B: 1024 float4
                int idx = tid + it * 256;
                int k = idx >> 4, c4 = (idx & 15) * 4;
                *(float4*)&Bs[h * PRE_B_HALF + k * 64 + c4] =
                    *(const float4*)&W1[(size_t)(kbase + k) * 128 + c0 + c4];
            }
        }
        __syncthreads();
        const float* Ah = &As[kh * PRE_A_HALF + (wr * 8 + rowg) * 68];
        const float* Bh = &Bs[kh * PRE_B_HALF + colg * 4];
#pragma unroll 4
        for (int kk = 0; kk < 64; kk++) {
            ulonglong2 w0 = *(const ulonglong2*)(Bh + kk * 64);
            ulonglong2 w1 = *(const ulonglong2*)(Bh + kk * 64 + 32);
#pragma unroll
            for (int j = 0; j < 2; j++) {
                unsigned long long xd = pack2s(Ah[j * 4 * 68 + kk]);
                ffma2(acc[j][0][0], xd, w0.x); ffma2(acc[j][0][1], xd, w0.y);
                ffma2(acc[j][1][0], xd, w1.x); ffma2(acc[j][1][1], xd, w1.y);
            }
        }
    }
    __syncthreads();
    if (kh == 1) {
#pragma unroll
        for (int j = 0; j < 2; j++) {
            int r = wr * 8 + rowg + 4 * j;
#pragma unroll
            for (int q = 0; q < 2; q++)
#pragma unroll
                for (int p = 0; p < 2; p++)
                    *(unsigned long long*)&pbuf[r * 66 + q * 32 + colg * 4 + 2 * p] =
                        acc[j][q][p];
        }
    }
    __syncthreads();
    if (kh == 0) {
#pragma unroll
        for (int j = 0; j < 2; j++) {
            int r = wr * 8 + rowg + 4 * j;
#pragma unroll
            for (int q = 0; q < 2; q++) {
                float2 a0 = unpack2(acc[j][q][0]), a1 = unpack2(acc[j][q][1]);
                float2 p0 = *(float2*)&pbuf[r * 66 + q * 32 + colg * 4];
                float2 p1 = *(float2*)&pbuf[r * 66 + q * 32 + colg * 4 + 2];
                float4 bv = *(const float4*)&b1[c0 + q * 32 + colg * 4];
                float4 o = make_float4(a0.x + p0.x + bv.x, a0.y + p0.y + bv.y,
                                       a1.x + p1.x + bv.z, a1.y + p1.y + bv.w);
                *(float4*)&g_hidpart[(size_t)(m0 + r) * 128 + c0 + q * 32 + colg * 4] = o;
            }
        }
    }
}

// ============================================================================
// Main kernel: persistent CTAs. Resident W (256x128). Tile TM=64 rows.
// 512 thr = 16 warps: kh(1b) x wc(1b) x wr(2b). Lane: rowg = l>>3, colg = l&7.
// Thread: rows wr*16+rowg+4j (j=0..3); cols wc*64 + q*32 + colg*4 + i (q=0,1).
// ============================================================================
#define W_OFF    0
#define X_OFF    32768          // x: [64][260]
#define X_PITCH  260
#define HB_PITCH 132            // hbuf aliases x region
#define ST_OFF   49408          // stat: [12][68]
#define WS_OFF   50224          // wsum: [12][128]
#define W2_OFF   51760          // w2:   [128][4]
#define RED_OFF  52272          // red:  [2*64][4]
#define SM_FLOATS 52784         // 211136 B

__global__ __launch_bounds__(512, 1) void main_kernel(
    const float* __restrict__ br0, const float* __restrict__ br1,
    const float* __restrict__ br2, const float* __restrict__ br3,
    const float* __restrict__ W1, const float* __restrict__ W2,
    const float* __restrict__ b2, const float* __restrict__ eps_floor,
    const float* __restrict__ temp, float* __restrict__ out)
{
    extern __shared__ float S[];
    int tid = threadIdx.x;
    int l = tid & 31, w = tid >> 5;
    int kh = w >> 3, wc = (w >> 2) & 1, wr = w & 3;
    int rowg = l >> 3, colg = l & 7;

    // one-time loads
    {
        const float4* Wb = (const float4*)(W1 + 1792 * 128);
        for (int i = tid; i < 32768 / 4; i += 512) ((float4*)&S[W_OFF])[i] = Wb[i];
        for (int i = tid; i < 12 * 128; i += 512) S[WS_OFF + i] = g_wsum[i];
        S[W2_OFF + tid] = W2[tid];
    }

    const int ntiles = NROWS / 64;   // 1024
    for (int tile = blockIdx.x; tile < ntiles; tile += gridDim.x) {
        int rg0 = tile * 64;
        __syncthreads();

        // ---- load x tile row-major: x[r][p*64+d] ----
        {
#pragma unroll
            for (int p = 0; p < 4; p++) {
                const float* bp = (p == 0) ? br0 : (p == 1) ? br1 : (p == 2) ? br2 : br3;
                const float4* bp4 = (const float4*)bp + (size_t)rg0 * 16;
#pragma unroll
                for (int it = 0; it < 2; it++) {
                    int idx = tid + it * 512;
                    int r = idx >> 4, d4 = (idx & 15) * 4;
                    *(float4*)&S[X_OFF + r * X_PITCH + p * 64 + d4] = bp4[idx];
                }
            }
        }
        __syncthreads();

        // ---- stats ----
        if (tid < 256) {
            int r = tid & 63, p = tid >> 6;
            const float* xr = &S[X_OFF + r * X_PITCH + p * 64];
            float sum = 0.f, sq = 0.f, mx = -INFINITY;
#pragma unroll
            for (int d4 = 0; d4 < 64; d4 += 4) {
                float4 v = *(const float4*)&xr[d4];
                sum += v.x + v.y + v.z + v.w;
                sq += v.x * v.x + v.y * v.y + v.z * v.z + v.w * v.w;
                mx = fmaxf(mx, fmaxf(fmaxf(v.x, v.y), fmaxf(v.z, v.w)));
            }
            S[ST_OFF + (p * 3 + 0) * 68 + r] = sum * (1.0f / 64.0f);
            S[ST_OFF + (p * 3 + 1) * 68 + r] = sqrtf(fmaxf(sq * (1.0f / 64.0f), 1e-8f));
            S[ST_OFF + (p * 3 + 2) * 68 + r] = mx;
        }
        __syncthreads();

        // ---- GEMM: k-half per kh ----
        unsigned long long acc[4][2][2];
#pragma unroll
        for (int j = 0; j < 4; j++)
#pragma unroll
            for (int q = 0; q < 2; q++) { acc[j][q][0] = 0ull; acc[j][q][1] = 0ull; }
        {
            const float* xr0 = &S[X_OFF + (wr * 16 + rowg) * X_PITCH];
            const float* Wp = &S[W_OFF + wc * 64 + colg * 4];
            int kbase = kh * 128;
#pragma unroll 2
            for (int k = kbase; k < kbase + 128; k++) {
                ulonglong2 w0 = *(const ulonglong2*)(Wp + k * 128);
                ulonglong2 w1 = *(const ulonglong2*)(Wp + k * 128 + 32);
#pragma unroll
                for (int j = 0; j < 4; j++) {
                    unsigned long long xd = pack2s(xr0[j * 4 * X_PITCH + k]);
                    ffma2(acc[j][0][0], xd, w0.x); ffma2(acc[j][0][1], xd, w0.y);
                    ffma2(acc[j][1][0], xd, w1.x); ffma2(acc[j][1][1], xd, w1.y);
                }
            }
        }
        __syncthreads();

        // ---- kh=1 stores its partial h into hbuf (aliases x) ----
        if (kh == 1) {
#pragma unroll
            for (int j = 0; j < 4; j++) {
                int r = wr * 16 + rowg + 4 * j;
#pragma unroll
                for (int q = 0; q < 2; q++)
#pragma unroll
                    for (int p = 0; p < 2; p++)
                        *(unsigned long long*)
                            &S[X_OFF + r * HB_PITCH + wc * 64 + q * 32 + colg * 4 + 2 * p] =
                            acc[j][q][p];
            }
        }
        __syncthreads();

        // ---- kh=0: combine + epilogue ----
        if (kh == 0) {
#pragma unroll
            for (int j = 0; j < 4; j++) {
                int r = wr * 16 + rowg + 4 * j;
                int rg = rg0 + r;
                float h[8];
#pragma unroll
                for (int q = 0; q < 2; q++)
#pragma unroll
                    for (int p = 0; p < 2; p++) {
                        float2 a = unpack2(acc[j][q][p]);
                        float2 pt = *(float2*)
                            &S[X_OFF + r * HB_PITCH + wc * 64 + q * 32 + colg * 4 + 2 * p];
                        h[q * 4 + 2 * p] = a.x + pt.x;
                        h[q * 4 + 2 * p + 1] = a.y + pt.y;
                    }
                const float* hp = &g_hidpart[(size_t)(rg >> 4) * 128 + wc * 64 + colg * 4];
                float4 hA = *(const float4*)hp;
                float4 hB = *(const float4*)(hp + 32);
                h[0] += hA.x; h[1] += hA.y; h[2] += hA.z; h[3] += hA.w;
                h[4] += hB.x; h[5] += hB.y; h[6] += hB.z; h[7] += hB.w;
#pragma unroll
                for (int ps = 0; ps < 12; ps++) {
                    float sv = S[ST_OFF + ps * 68 + r];
                    float4 wA = *(const float4*)&S[WS_OFF + ps * 128 + wc * 64 + colg * 4];
                    float4 wB = *(const float4*)&S[WS_OFF + ps * 128 + wc * 64 + 32 + colg * 4];
                    h[0] += sv * wA.x; h[1] += sv * wA.y; h[2] += sv * wA.z; h[3] += sv * wA.w;
                    h[4] += sv * wB.x; h[5] += sv * wB.y; h[6] += sv * wB.z; h[7] += sv * wB.w;
                }
                float lp0 = 0.f, lp1 = 0.f, lp2 = 0.f, lp3 = 0.f;
#pragma unroll
                for (int c = 0; c < 8; c++) {
                    int cc = wc * 64 + ((c >= 4) ? 32 : 0) + colg * 4 + (c & 3);
                    float gv = 0.5f * h[c] * (1.0f + erff(h[c] * 0.7071067811865476f));
                    float4 w2v = *(const float4*)&S[W2_OFF + cc * 4];
                    lp0 += gv * w2v.x; lp1 += gv * w2v.y;
                    lp2 += gv * w2v.z; lp3 += gv * w2v.w;
                }
#pragma unroll
                for (int off = 1; off < 8; off <<= 1) {
                    lp0 += __shfl_xor_sync(0xffffffffu, lp0, off);
                    lp1 += __shfl_xor_sync(0xffffffffu, lp1, off);
                    lp2 += __shfl_xor_sync(0xffffffffu, lp2, off);
                    lp3 += __shfl_xor_sync(0xffffffffu, lp3, off);
                }
                if (colg == 0)
                    *(float4*)&S[RED_OFF + (wc * 64 + r) * 4] =
                        make_float4(lp0, lp1, lp2, lp3);
            }
        }
        __syncthreads();

        // ---- final: sum wc halves, softmax, floor, renorm, store ----
        if (tid < 256) {
            int r = tid >> 2, n = tid & 3;
            float s = S[RED_OFF + r * 4 + n] + S[RED_OFF + (64 + r) * 4 + n] + b2[n];
            int rg = rg0 + r;
            int hh = rg & (HH - 1);
            float t = fminf(fmaxf(temp[hh], 0.2f), 10.0f);
            float q = s / t;
            float m = q;
            m = fmaxf(m, __shfl_xor_sync(0xffffffffu, m, 1));
            m = fmaxf(m, __shfl_xor_sync(0xffffffffu, m, 2));
            float ev = expf(q - m);
            float se = ev;
            se += __shfl_xor_sync(0xffffffffu, se, 1);
            se += __shfl_xor_sync(0xffffffffu, se, 2);
            float wv = ev / se;
            float fl = fminf(fmaxf(eps_floor[hh * 4 + n], 1e-7f), 0.1f);
            wv = fmaxf(wv, fl);
            float sw = wv;
            sw += __shfl_xor_sync(0xffffffffu, sw, 1);
            sw += __shfl_xor_sync(0xffffffffu, sw, 2);
            out[(size_t)rg * 4 + n] = wv / sw;
        }
    }
}

// ============================================================================
// Launch
// ============================================================================
extern "C" void kernel_launch(void* const* d_in, const int* in_sizes, int n_in,
                              void* d_out, int out_size)
{
    const float* hidden = (const float*)d_in[0];
    const float* br0    = (const float*)d_in[1];
    const float* br1    = (const float*)d_in[2];
    const float* br2    = (const float*)d_in[3];
    const float* br3    = (const float*)d_in[4];
    const float* W1     = (const float*)d_in[5];
    const float* b1     = (const float*)d_in[6];
    const float* W2     = (const float*)d_in[7];
    const float* b2     = (const float*)d_in[8];
    const float* eps    = (const float*)d_in[9];
    const float* temp   = (const float*)d_in[10];
    float* out = (float*)d_out;

    cudaFuncSetAttribute(pre_kernel, cudaFuncAttributeMaxDynamicSharedMemorySize,
                         PRE_SMEM_FLOATS * 4);
    cudaFuncSetAttribute(main_kernel, cudaFuncAttributeMaxDynamicSharedMemorySize,
                         SM_FLOATS * 4);

    pre_kernel<<<268, 256, PRE_SMEM_FLOATS * 4>>>(hidden, W1, b1);
    main_kernel<<<148, 512, SM_FLOATS * 4>>>(br0, br1, br2, br3, W1, W2,
                                             b2, eps, temp, out);
}

// round 7
// speedup vs baseline: 1.7981x; 1.3581x over previous
#include <cuda_runtime.h>
#include <math.h>
#include <stdint.h>

#define HH    16
#define NROWS 65536
#define NBL   4096

__device__ float g_wsum[12 * 128];
__device__ float g_hidpart[NBL * 128];   // hidden @ W1[0:1024]  (b1 added here)

// ---- packed fp32x2 helpers ----
__device__ __forceinline__ void ffma2(unsigned long long& d,
                                      unsigned long long a,
                                      unsigned long long b) {
    asm("fma.rn.f32x2 %0, %1, %2, %0;" : "+l"(d) : "l"(a), "l"(b));
}
__device__ __forceinline__ unsigned long long pack2s(float x) {
    unsigned long long r;
    asm("mov.b64 %0, {%1, %1};" : "=l"(r) : "f"(x));
    return r;
}
__device__ __forceinline__ float2 unpack2(unsigned long long v) {
    float2 f;
    asm("mov.b64 {%0, %1}, %2;" : "=f"(f.x), "=f"(f.y) : "l"(v));
    return f;
}

// ============================================================================
// Pre-kernel: blocks 0..255 = hidden GEMM (Mtile 32 x Ntile 64, k-split 2)
//             blocks 256..267 = wsum     (unchanged from R6)
// ============================================================================
#define PRE_A_HALF (32 * 68)
#define PRE_B_HALF (64 * 64)
#define PRE_SMEM_FLOATS (2 * PRE_A_HALF + 2 * PRE_B_HALF)   // 12544 -> 50176 B

__global__ __launch_bounds__(256) void pre_kernel(
    const float* __restrict__ hidden,
    const float* __restrict__ W1,
    const float* __restrict__ b1)
{
    if (blockIdx.x >= 256) {
        int ps = blockIdx.x - 256;
        if (threadIdx.x < 128) {
            int j = threadIdx.x;
            int base = 1024 + ps * 64;
            float s = 0.f;
#pragma unroll
            for (int d = 0; d < 64; d++) s += W1[(base + d) * 128 + j];
            g_wsum[ps * 128 + j] = s;
        }
        return;
    }

    extern __shared__ float sm[];
    float* As = sm;
    float* Bs = sm + 2 * PRE_A_HALF;
    float* pbuf = sm;

    int tid = threadIdx.x;
    int l = tid & 31, w = tid >> 5;
    int kh = w >> 2, wr = w & 3;
    int rowg = l >> 3, colg = l & 7;
    int m0 = (blockIdx.x >> 1) * 32;
    int c0 = (blockIdx.x & 1) * 64;

    unsigned long long acc[2][2][2];
#pragma unroll
    for (int j = 0; j < 2; j++)
#pragma unroll
        for (int q = 0; q < 2; q++) { acc[j][q][0] = 0ull; acc[j][q][1] = 0ull; }

    for (int t = 0; t < 8; t++) {
        __syncthreads();
#pragma unroll
        for (int h = 0; h < 2; h++) {
            int kbase = h * 512 + t * 64;
#pragma unroll
            for (int it = 0; it < 2; it++) {
                int idx = tid + it * 256;
                int r = idx >> 4, k4 = (idx & 15) * 4;
                *(float4*)&As[h * PRE_A_HALF + r * 68 + k4] =
                    *(const float4*)&hidden[(size_t)(m0 + r) * 1024 + kbase + k4];
            }
#pragma unroll
            for (int it = 0; it < 4; it++) {
                int idx = tid + it * 256;
                int k = idx >> 4, c4 = (idx & 15) * 4;
                *(float4*)&Bs[h * PRE_B_HALF + k * 64 + c4] =
                    *(const float4*)&W1[(size_t)(kbase + k) * 128 + c0 + c4];
            }
        }
        __syncthreads();
        const float* Ah = &As[kh * PRE_A_HALF + (wr * 8 + rowg) * 68];
        const float* Bh = &Bs[kh * PRE_B_HALF + colg * 4];
#pragma unroll 4
        for (int kk = 0; kk < 64; kk++) {
            ulonglong2 w0 = *(const ulonglong2*)(Bh + kk * 64);
            ulonglong2 w1 = *(const ulonglong2*)(Bh + kk * 64 + 32);
#pragma unroll
            for (int j = 0; j < 2; j++) {
                unsigned long long xd = pack2s(Ah[j * 4 * 68 + kk]);
                ffma2(acc[j][0][0], xd, w0.x); ffma2(acc[j][0][1], xd, w0.y);
                ffma2(acc[j][1][0], xd, w1.x); ffma2(acc[j][1][1], xd, w1.y);
            }
        }
    }
    __syncthreads();
    if (kh == 1) {
#pragma unroll
        for (int j = 0; j < 2; j++) {
            int r = wr * 8 + rowg + 4 * j;
#pragma unroll
            for (int q = 0; q < 2; q++)
#pragma unroll
                for (int p = 0; p < 2; p++)
                    *(unsigned long long*)&pbuf[r * 66 + q * 32 + colg * 4 + 2 * p] =
                        acc[j][q][p];
        }
    }
    __syncthreads();
    if (kh == 0) {
#pragma unroll
        for (int j = 0; j < 2; j++) {
            int r = wr * 8 + rowg + 4 * j;
#pragma unroll
            for (int q = 0; q < 2; q++) {
                float2 a0 = unpack2(acc[j][q][0]), a1 = unpack2(acc[j][q][1]);
                float2 p0 = *(float2*)&pbuf[r * 66 + q * 32 + colg * 4];
                float2 p1 = *(float2*)&pbuf[r * 66 + q * 32 + colg * 4 + 2];
                float4 bv = *(const float4*)&b1[c0 + q * 32 + colg * 4];
                float4 o = make_float4(a0.x + p0.x + bv.x, a0.y + p0.y + bv.y,
                                       a1.x + p1.x + bv.z, a1.y + p1.y + bv.w);
                *(float4*)&g_hidpart[(size_t)(m0 + r) * 128 + c0 + q * 32 + colg * 4] = o;
            }
        }
    }
}

// ============================================================================
// Main kernel: persistent CTAs. Resident W (256x128). Tile TM=64 rows.
// GEMM phase: 16 warps = kh(1) x wc(1) x wr(2); thread = 4 rows x 8 cols.
// acc -> hbuf (both halves), then a separate low-register epilogue where
// thread = (row, 16-col chunk) and the 8-lane reduction finishes the row.
// ============================================================================
#define W_OFF    0
#define X_OFF    32768          // x: [64][264]  (aliased by hbuf [2][64][132])
#define X_PITCH  264
#define HB_PITCH 132
#define HB_HALF  8448           // 64*132
#define ST_OFF   49664          // stat: [12][68]
#define WS_OFF   50480          // wsum: [12][128]
#define W2T_OFF  52016          // w2T:  [4][132]
#define SM_FLOATS 52544         // 210176 B

__global__ __launch_bounds__(512, 1) void main_kernel(
    const float* __restrict__ br0, const float* __restrict__ br1,
    const float* __restrict__ br2, const float* __restrict__ br3,
    const float* __restrict__ W1, const float* __restrict__ W2,
    const float* __restrict__ b2, const float* __restrict__ eps_floor,
    const float* __restrict__ temp, float* __restrict__ out)
{
    extern __shared__ float S[];
    int tid = threadIdx.x;
    int l = tid & 31, w = tid >> 5;
    int kh = w >> 3, wc = (w >> 2) & 1, wr = w & 3;
    int rowg = l >> 3, colg = l & 7;

    // one-time loads
    {
        const float4* Wb = (const float4*)(W1 + 1792 * 128);
        for (int i = tid; i < 32768 / 4; i += 512) ((float4*)&S[W_OFF])[i] = Wb[i];
        for (int i = tid; i < 12 * 128; i += 512) S[WS_OFF + i] = g_wsum[i];
        if (tid < 512) {                       // w2 transposed: w2T[n][c]
            int c = tid >> 2, n = tid & 3;
            S[W2T_OFF + n * 132 + c] = W2[c * 4 + n];
        }
    }

    const int ntiles = NROWS / 64;   // 1024
    for (int tile = blockIdx.x; tile < ntiles; tile += gridDim.x) {
        int rg0 = tile * 64;
        __syncthreads();   // prev epilogue hbuf reads done; one-time loads on iter 0

        // ---- load x tile row-major: x[r][p*64+d], pitch 264 ----
#pragma unroll
        for (int p = 0; p < 4; p++) {
            const float* bp = (p == 0) ? br0 : (p == 1) ? br1 : (p == 2) ? br2 : br3;
            const float4* bp4 = (const float4*)bp + (size_t)rg0 * 16;
#pragma unroll
            for (int it = 0; it < 2; it++) {
                int idx = tid + it * 512;
                int r = idx >> 4, d4 = (idx & 15) * 4;
                *(float4*)&S[X_OFF + r * X_PITCH + p * 64 + d4] = bp4[idx];
            }
        }
        __syncthreads();

        // ---- stats (256 threads) ----
        if (tid < 256) {
            int r = tid & 63, p = tid >> 6;
            const float* xr = &S[X_OFF + r * X_PITCH + p * 64];
            float sum = 0.f, sq = 0.f, mx = -INFINITY;
#pragma unroll
            for (int d4 = 0; d4 < 64; d4 += 4) {
                float4 v = *(const float4*)&xr[d4];
                sum += v.x + v.y + v.z + v.w;
                sq += v.x * v.x + v.y * v.y + v.z * v.z + v.w * v.w;
                mx = fmaxf(mx, fmaxf(fmaxf(v.x, v.y), fmaxf(v.z, v.w)));
            }
            S[ST_OFF + (p * 3 + 0) * 68 + r] = sum * (1.0f / 64.0f);
            S[ST_OFF + (p * 3 + 1) * 68 + r] = sqrtf(fmaxf(sq * (1.0f / 64.0f), 1e-8f));
            S[ST_OFF + (p * 3 + 2) * 68 + r] = mx;
        }

        // ---- GEMM: k-half per kh; thread = rows wr*16+rowg+4j, cols wc*64+q*32+colg*4 ----
        unsigned long long acc[4][2][2];
#pragma unroll
        for (int j = 0; j < 4; j++)
#pragma unroll
            for (int q = 0; q < 2; q++) { acc[j][q][0] = 0ull; acc[j][q][1] = 0ull; }
        {
            const float* xr0 = &S[X_OFF + (wr * 16 + rowg) * X_PITCH];
            const float* Wp = &S[W_OFF + wc * 64 + colg * 4];
            int kbase = kh * 128;
#pragma unroll 2
            for (int k = kbase; k < kbase + 128; k++) {
                ulonglong2 w0 = *(const ulonglong2*)(Wp + k * 128);
                ulonglong2 w1 = *(const ulonglong2*)(Wp + k * 128 + 32);
#pragma unroll
                for (int j = 0; j < 4; j++) {
                    unsigned long long xd = pack2s(xr0[j * 4 * X_PITCH + k]);
                    ffma2(acc[j][0][0], xd, w0.x); ffma2(acc[j][0][1], xd, w0.y);
                    ffma2(acc[j][1][0], xd, w1.x); ffma2(acc[j][1][1], xd, w1.y);
                }
            }
        }
        __syncthreads();   // all x reads done -> hbuf may overwrite x region

        // ---- store acc -> hbuf[kh][r][col] (acc dies here) ----
#pragma unroll
        for (int j = 0; j < 4; j++) {
            int r = wr * 16 + rowg + 4 * j;
            float* hb = &S[X_OFF + kh * HB_HALF + r * HB_PITCH + wc * 64 + colg * 4];
#pragma unroll
            for (int q = 0; q < 2; q++)
#pragma unroll
                for (int p = 0; p < 2; p++)
                    *(unsigned long long*)&hb[q * 32 + 2 * p] = acc[j][q][p];
        }
        __syncthreads();

        // ---- epilogue: thread = (row r, 16-col chunk) ----
        {
            int r = tid >> 3;
            int c0 = (tid & 7) * 16;
            int rg = rg0 + r;
            float h[16];
#pragma unroll
            for (int i = 0; i < 4; i++) {
                float4 a = *(const float4*)&S[X_OFF + r * HB_PITCH + c0 + 4 * i];
                float4 b = *(const float4*)&S[X_OFF + HB_HALF + r * HB_PITCH + c0 + 4 * i];
                float4 v = *(const float4*)&g_hidpart[(size_t)(rg >> 4) * 128 + c0 + 4 * i];
                h[4 * i + 0] = a.x + b.x + v.x;
                h[4 * i + 1] = a.y + b.y + v.y;
                h[4 * i + 2] = a.z + b.z + v.z;
                h[4 * i + 3] = a.w + b.w + v.w;
            }
#pragma unroll
            for (int ps = 0; ps < 12; ps++) {
                float sv = S[ST_OFF + ps * 68 + r];
#pragma unroll
                for (int i = 0; i < 4; i++) {
                    float4 wv = *(const float4*)&S[WS_OFF + ps * 128 + c0 + 4 * i];
                    h[4 * i + 0] += sv * wv.x; h[4 * i + 1] += sv * wv.y;
                    h[4 * i + 2] += sv * wv.z; h[4 * i + 3] += sv * wv.w;
                }
            }
            float lp0 = 0.f, lp1 = 0.f, lp2 = 0.f, lp3 = 0.f;
#pragma unroll
            for (int i = 0; i < 4; i++) {
                float g0 = 0.5f * h[4*i+0] * (1.0f + erff(h[4*i+0] * 0.7071067811865476f));
                float g1 = 0.5f * h[4*i+1] * (1.0f + erff(h[4*i+1] * 0.7071067811865476f));
                float g2 = 0.5f * h[4*i+2] * (1.0f + erff(h[4*i+2] * 0.7071067811865476f));
                float g3 = 0.5f * h[4*i+3] * (1.0f + erff(h[4*i+3] * 0.7071067811865476f));
                float4 wa = *(const float4*)&S[W2T_OFF + 0 * 132 + c0 + 4 * i];
                float4 wb = *(const float4*)&S[W2T_OFF + 1 * 132 + c0 + 4 * i];
                float4 wc4 = *(const float4*)&S[W2T_OFF + 2 * 132 + c0 + 4 * i];
                float4 wd = *(const float4*)&S[W2T_OFF + 3 * 132 + c0 + 4 * i];
                lp0 += g0 * wa.x + g1 * wa.y + g2 * wa.z + g3 * wa.w;
                lp1 += g0 * wb.x + g1 * wb.y + g2 * wb.z + g3 * wb.w;
                lp2 += g0 * wc4.x + g1 * wc4.y + g2 * wc4.z + g3 * wc4.w;
                lp3 += g0 * wd.x + g1 * wd.y + g2 * wd.z + g3 * wd.w;
            }
#pragma unroll
            for (int off = 1; off < 8; off <<= 1) {
                lp0 += __shfl_xor_sync(0xffffffffu, lp0, off);
                lp1 += __shfl_xor_sync(0xffffffffu, lp1, off);
                lp2 += __shfl_xor_sync(0xffffffffu, lp2, off);
                lp3 += __shfl_xor_sync(0xffffffffu, lp3, off);
            }
            if ((tid & 7) == 0) {
                int hh = rg & (HH - 1);
                float t = fminf(fmaxf(temp[hh], 0.2f), 10.0f);
                float invt = 1.0f / t;
                float q0 = (lp0 + b2[0]) * invt;
                float q1 = (lp1 + b2[1]) * invt;
                float q2 = (lp2 + b2[2]) * invt;
                float q3 = (lp3 + b2[3]) * invt;
                float m = fmaxf(fmaxf(q0, q1), fmaxf(q2, q3));
                float e0 = expf(q0 - m), e1 = expf(q1 - m);
                float e2 = expf(q2 - m), e3 = expf(q3 - m);
                float inv = 1.0f / (e0 + e1 + e2 + e3);
                float w0 = e0 * inv, w1 = e1 * inv, w2v = e2 * inv, w3 = e3 * inv;
                const float* ef = eps_floor + hh * 4;
                w0 = fmaxf(w0, fminf(fmaxf(ef[0], 1e-7f), 0.1f));
                w1 = fmaxf(w1, fminf(fmaxf(ef[1], 1e-7f), 0.1f));
                w2v = fmaxf(w2v, fminf(fmaxf(ef[2], 1e-7f), 0.1f));
                w3 = fmaxf(w3, fminf(fmaxf(ef[3], 1e-7f), 0.1f));
                float inv2 = 1.0f / (w0 + w1 + w2v + w3);
                *(float4*)&out[(size_t)rg * 4] =
                    make_float4(w0 * inv2, w1 * inv2, w2v * inv2, w3 * inv2);
            }
        }
    }
}

// ============================================================================
// Launch
// ============================================================================
extern "C" void kernel_launch(void* const* d_in, const int* in_sizes, int n_in,
                              void* d_out, int out_size)
{
    const float* hidden = (const float*)d_in[0];
    const float* br0    = (const float*)d_in[1];
    const float* br1    = (const float*)d_in[2];
    const float* br2    = (const float*)d_in[3];
    const float* br3    = (const float*)d_in[4];
    const float* W1     = (const float*)d_in[5];
    const float* b1     = (const float*)d_in[6];
    const float* W2     = (const float*)d_in[7];
    const float* b2     = (const float*)d_in[8];
    const float* eps    = (const float*)d_in[9];
    const float* temp   = (const float*)d_in[10];
    float* out = (float*)d_out;

    cudaFuncSetAttribute(pre_kernel, cudaFuncAttributeMaxDynamicSharedMemorySize,
                         PRE_SMEM_FLOATS * 4);
    cudaFuncSetAttribute(main_kernel, cudaFuncAttributeMaxDynamicSharedMemorySize,
                         SM_FLOATS * 4);

    pre_kernel<<<268, 256, PRE_SMEM_FLOATS * 4>>>(hidden, W1, b1);
    main_kernel<<<148, 512, SM_FLOATS * 4>>>(br0, br1, br2, br3, W1, W2,
                                             b2, eps, temp, out);
}

// round 8
// speedup vs baseline: 1.9366x; 1.0770x over previous
#include <cuda_runtime.h>
#include <math.h>
#include <stdint.h>

#define HH    16
#define NROWS 65536
#define NBL   4096

__device__ float g_wsum[12 * 128];
__device__ float g_hidpart[NBL * 128];   // hidden @ W1[0:1024] + b1

// ---- packed fp32x2 helpers ----
__device__ __forceinline__ void ffma2(unsigned long long& d,
                                      unsigned long long a,
                                      unsigned long long b) {
    asm("fma.rn.f32x2 %0, %1, %2, %0;" : "+l"(d) : "l"(a), "l"(b));
}
__device__ __forceinline__ unsigned long long addf32x2(unsigned long long a,
                                                       unsigned long long b) {
    unsigned long long r;
    asm("add.rn.f32x2 %0, %1, %2;" : "=l"(r) : "l"(a), "l"(b));
    return r;
}
__device__ __forceinline__ unsigned long long pack2s(float x) {
    unsigned long long r;
    asm("mov.b64 %0, {%1, %1};" : "=l"(r) : "f"(x));
    return r;
}

// ============================================================================
// Pre-kernel: blocks 0..255 = hidden GEMM (Mtile 32 x Ntile 64, k-split 4)
//             blocks 256..267 = wsum
// 256 thr = 8 warps: kh = w>>1 (0..3), wr = w&1. Lane: rowg=l>>3(0..3), colg=l&7.
// Thread: rows wr*16+rowg+4j (j<4); cols colg*4 + q*32 (q<2). R=4, C=8.
// ============================================================================
#define PRE_A_HALF (32 * 68)     // 2176 floats per half
#define PRE_B_HALF (64 * 64)     // 4096 floats per half
#define PRE_SMEM_FLOATS (2 * PRE_A_HALF + 2 * PRE_B_HALF)   // 12544 -> 50176 B

__global__ __launch_bounds__(256) void pre_kernel(
    const float* __restrict__ hidden,
    const float* __restrict__ W1,
    const float* __restrict__ b1)
{
    if (blockIdx.x >= 256) {
        int ps = blockIdx.x - 256;
        if (threadIdx.x < 128) {
            int j = threadIdx.x;
            int base = 1024 + ps * 64;
            float s = 0.f;
#pragma unroll
            for (int d = 0; d < 64; d++) s += W1[(base + d) * 128 + j];
            g_wsum[ps * 128 + j] = s;
        }
        return;
    }

    extern __shared__ float sm[];
    float* As = sm;                       // [2][32][68]
    float* Bs = sm + 2 * PRE_A_HALF;      // [2][64][64]
    float* pbuf = sm;                     // alias: 2 halves of [32][68]

    int tid = threadIdx.x;
    int l = tid & 31, w = tid >> 5;
    int kh = w >> 1, wr = w & 1;
    int rowg = l >> 3, colg = l & 7;

    unsigned long long acc[4][2][2];      // [j row][q quad][pair]
#pragma unroll
    for (int j = 0; j < 4; j++)
#pragma unroll
        for (int q = 0; q < 2; q++) { acc[j][q][0] = 0ull; acc[j][q][1] = 0ull; }

    int m0 = (blockIdx.x >> 1) * 32;
    int c0 = (blockIdx.x & 1) * 64;

    for (int t = 0; t < 8; t++) {
        __syncthreads();
#pragma unroll
        for (int h = 0; h < 2; h++) {
            int kbase = t * 128 + h * 64;
#pragma unroll
            for (int it = 0; it < 2; it++) {       // A: 512 float4
                int idx = tid + it * 256;
                int r = idx >> 4, k4 = (idx & 15) * 4;
                *(float4*)&As[h * PRE_A_HALF + r * 68 + k4] =
                    *(const float4*)&hidden[(size_t)(m0 + r) * 1024 + kbase + k4];
            }
#pragma unroll
            for (int it = 0; it < 4; it++) {       // B: 1024 float4
                int idx = tid + it * 256;
                int k = idx >> 4, c4 = (idx & 15) * 4;
                *(float4*)&Bs[h * PRE_B_HALF + k * 64 + c4] =
                    *(const float4*)&W1[(size_t)(kbase + k) * 128 + c0 + c4];
            }
        }
        __syncthreads();
        int half = kh >> 1, sub = kh & 1;
        const float* Ah = &As[half * PRE_A_HALF + (wr * 16 + rowg) * 68 + sub * 32];
        const float* Bh = &Bs[half * PRE_B_HALF + sub * 32 * 64 + colg * 4];
#pragma unroll 4
        for (int kk = 0; kk < 32; kk++) {
            ulonglong2 w0 = *(const ulonglong2*)(Bh + kk * 64);
            ulonglong2 w1 = *(const ulonglong2*)(Bh + kk * 64 + 32);
#pragma unroll
            for (int j = 0; j < 4; j++) {
                unsigned long long xd = pack2s(Ah[j * 4 * 68 + kk]);
                ffma2(acc[j][0][0], xd, w0.x); ffma2(acc[j][0][1], xd, w0.y);
                ffma2(acc[j][1][0], xd, w1.x); ffma2(acc[j][1][1], xd, w1.y);
            }
        }
    }
    __syncthreads();
    // ---- 4-way k reduce: kh1 -> half0, kh3 -> half1 ----
    if (kh & 1) {
        int part = kh >> 1;
#pragma unroll
        for (int j = 0; j < 4; j++) {
            int r = wr * 16 + rowg + 4 * j;
#pragma unroll
            for (int q = 0; q < 2; q++)
#pragma unroll
                for (int p = 0; p < 2; p++)
                    *(unsigned long long*)&pbuf[part * 2176 + r * 68 + colg * 4 + q * 32 + 2 * p] =
                        acc[j][q][p];
        }
    }
    __syncthreads();
    if (!(kh & 1)) {
        int part = kh >> 1;
#pragma unroll
        for (int j = 0; j < 4; j++) {
            int r = wr * 16 + rowg + 4 * j;
#pragma unroll
            for (int q = 0; q < 2; q++)
#pragma unroll
                for (int p = 0; p < 2; p++) {
                    unsigned long long* a =
                        (unsigned long long*)&pbuf[part * 2176 + r * 68 + colg * 4 + q * 32 + 2 * p];
                    *a = addf32x2(*a, acc[j][q][p]);
                }
        }
    }
    __syncthreads();
    // ---- final write: half0 + half1 + b1 -> g_hidpart ----
#pragma unroll
    for (int it = 0; it < 2; it++) {
        int idx = tid + it * 256;            // 512 float4
        int r = idx >> 4, c4 = (idx & 15) * 4;
        float4 h0 = *(const float4*)&pbuf[r * 68 + c4];
        float4 h1 = *(const float4*)&pbuf[2176 + r * 68 + c4];
        float4 bv = *(const float4*)&b1[c0 + c4];
        float4 o = make_float4(h0.x + h1.x + bv.x, h0.y + h1.y + bv.y,
                               h0.z + h1.z + bv.z, h0.w + h1.w + bv.w);
        *(float4*)&g_hidpart[(size_t)(m0 + r) * 128 + c0 + c4] = o;
    }
}

// ============================================================================
// Main kernel: persistent CTAs. Resident W (256x128). Tile TM=64 rows.
// 16 warps: kh = w>>2 (4-way k-split, 64 k each), wc = w&3 (32-col groups).
// Lane: rowg = l>>2 (0..7), colg = l&3. Thread: rows rowg+8j (j<8),
// cols wc*32 + colg*8 + {0..7}.  R=8, C=8: phases 16 = FFMA2 budget 16.
// acc -> 2-level tree reduce in hbuf (aliases x, parts at +0/+128 per row).
// ============================================================================
#define W_OFF    0
#define X_OFF    32768          // x: [64][260]  (hbuf aliases: [r][part*128+c])
#define X_PITCH  260
#define ST_OFF   49408          // stat: [12][68]
#define WS_OFF   50224          // wsum: [12][128]
#define W2T_OFF  51760          // w2T:  [4][132]
#define SM_FLOATS 52288         // 209152 B

__global__ __launch_bounds__(512, 1) void main_kernel(
    const float* __restrict__ br0, const float* __restrict__ br1,
    const float* __restrict__ br2, const float* __restrict__ br3,
    const float* __restrict__ W1, const float* __restrict__ W2,
    const float* __restrict__ b2, const float* __restrict__ eps_floor,
    const float* __restrict__ temp, float* __restrict__ out)
{
    extern __shared__ float S[];
    int tid = threadIdx.x;
    int l = tid & 31, w = tid >> 5;
    int kh = w >> 2, wc = w & 3;
    int rowg = l >> 2, colg = l & 3;

    // one-time loads
    {
        const float4* Wb = (const float4*)(W1 + 1792 * 128);
        for (int i = tid; i < 32768 / 4; i += 512) ((float4*)&S[W_OFF])[i] = Wb[i];
        for (int i = tid; i < 12 * 128; i += 512) S[WS_OFF + i] = g_wsum[i];
        {
            int c = tid >> 2, n = tid & 3;     // w2 transposed: w2T[n][c]
            S[W2T_OFF + n * 132 + c] = W2[c * 4 + n];
        }
    }

    const int ntiles = NROWS / 64;   // 1024
    for (int tile = blockIdx.x; tile < ntiles; tile += gridDim.x) {
        int rg0 = tile * 64;
        __syncthreads();   // prev epilogue hbuf/stat reads done; one-time loads iter 0

        // ---- load x tile row-major: x[r][p*64+d], pitch 260 ----
#pragma unroll
        for (int p = 0; p < 4; p++) {
            const float* bp = (p == 0) ? br0 : (p == 1) ? br1 : (p == 2) ? br2 : br3;
            const float4* bp4 = (const float4*)bp + (size_t)rg0 * 16;
#pragma unroll
            for (int it = 0; it < 2; it++) {
                int idx = tid + it * 512;
                int r = idx >> 4, d4 = (idx & 15) * 4;
                *(float4*)&S[X_OFF + r * X_PITCH + p * 64 + d4] = bp4[idx];
            }
        }
        __syncthreads();

        // ---- stats (256 threads; overlaps with GEMM issue) ----
        if (tid < 256) {
            int r = tid & 63, p = tid >> 6;
            const float* xr = &S[X_OFF + r * X_PITCH + p * 64];
            float sum = 0.f, sq = 0.f, mx = -INFINITY;
#pragma unroll
            for (int d4 = 0; d4 < 64; d4 += 4) {
                float4 v = *(const float4*)&xr[d4];
                sum += v.x + v.y + v.z + v.w;
                sq += v.x * v.x + v.y * v.y + v.z * v.z + v.w * v.w;
                mx = fmaxf(mx, fmaxf(fmaxf(v.x, v.y), fmaxf(v.z, v.w)));
            }
            S[ST_OFF + (p * 3 + 0) * 68 + r] = sum * (1.0f / 64.0f);
            S[ST_OFF + (p * 3 + 1) * 68 + r] = sqrtf(fmaxf(sq * (1.0f / 64.0f), 1e-8f));
            S[ST_OFF + (p * 3 + 2) * 68 + r] = mx;
        }

        // ---- GEMM: 64 k per warp; thread 8 rows x 8 cols ----
        unsigned long long acc[8][4];
#pragma unroll
        for (int j = 0; j < 8; j++)
#pragma unroll
            for (int c = 0; c < 4; c++) acc[j][c] = 0ull;
        {
            const float* xr0 = &S[X_OFF + rowg * X_PITCH];
            const float* Wp = &S[W_OFF + wc * 32 + colg * 8];
            int kbase = kh * 64;
#pragma unroll 2
            for (int kk = 0; kk < 64; kk++) {
                int k = kbase + kk;
                ulonglong2 w01 = *(const ulonglong2*)(Wp + k * 128);
                ulonglong2 w23 = *(const ulonglong2*)(Wp + k * 128 + 4);
#pragma unroll
                for (int j = 0; j < 8; j++) {
                    unsigned long long xd = pack2s(xr0[j * 8 * X_PITCH + k]);
                    ffma2(acc[j][0], xd, w01.x); ffma2(acc[j][1], xd, w01.y);
                    ffma2(acc[j][2], xd, w23.x); ffma2(acc[j][3], xd, w23.y);
                }
            }
        }
        __syncthreads();   // x reads done -> hbuf may overwrite x region

        // ---- tree reduce level 1: kh1 -> part0, kh3 -> part1 ----
        if (kh & 1) {
            int part = kh >> 1;
#pragma unroll
            for (int j = 0; j < 8; j++) {
                float* hb = &S[X_OFF + (rowg + 8 * j) * X_PITCH + part * 128
                               + wc * 32 + colg * 8];
#pragma unroll
                for (int c = 0; c < 4; c++)
                    *(unsigned long long*)&hb[2 * c] = acc[j][c];
            }
        }
        __syncthreads();

        // ---- level 2: kh0 += part0, kh2 += part1 (write back) ----
        if (!(kh & 1)) {
            int part = kh >> 1;
#pragma unroll
            for (int j = 0; j < 8; j++) {
                float* hb = &S[X_OFF + (rowg + 8 * j) * X_PITCH + part * 128
                               + wc * 32 + colg * 8];
#pragma unroll
                for (int c = 0; c < 4; c++) {
                    unsigned long long* a = (unsigned long long*)&hb[2 * c];
                    *a = addf32x2(*a, acc[j][c]);
                }
            }
        }
        __syncthreads();

        // ---- epilogue: thread = (row r, 16-col chunk); h = part0 + part1 ----
        {
            int r = tid >> 3;
            int c0 = (tid & 7) * 16;
            int rg = rg0 + r;
            float h[16];
#pragma unroll
            for (int i = 0; i < 4; i++) {
                float4 a = *(const float4*)&S[X_OFF + r * X_PITCH + c0 + 4 * i];
                float4 b = *(const float4*)&S[X_OFF + r * X_PITCH + 128 + c0 + 4 * i];
                float4 v = *(const float4*)&g_hidpart[(size_t)(rg >> 4) * 128 + c0 + 4 * i];
                h[4 * i + 0] = a.x + b.x + v.x;
                h[4 * i + 1] = a.y + b.y + v.y;
                h[4 * i + 2] = a.z + b.z + v.z;
                h[4 * i + 3] = a.w + b.w + v.w;
            }
#pragma unroll
            for (int ps = 0; ps < 12; ps++) {
                float sv = S[ST_OFF + ps * 68 + r];
#pragma unroll
                for (int i = 0; i < 4; i++) {
                    float4 wv = *(const float4*)&S[WS_OFF + ps * 128 + c0 + 4 * i];
                    h[4 * i + 0] += sv * wv.x; h[4 * i + 1] += sv * wv.y;
                    h[4 * i + 2] += sv * wv.z; h[4 * i + 3] += sv * wv.w;
                }
            }
            float lp0 = 0.f, lp1 = 0.f, lp2 = 0.f, lp3 = 0.f;
#pragma unroll
            for (int i = 0; i < 4; i++) {
                float g0 = 0.5f * h[4*i+0] * (1.0f + erff(h[4*i+0] * 0.7071067811865476f));
                float g1 = 0.5f * h[4*i+1] * (1.0f + erff(h[4*i+1] * 0.7071067811865476f));
                float g2 = 0.5f * h[4*i+2] * (1.0f + erff(h[4*i+2] * 0.7071067811865476f));
                float g3 = 0.5f * h[4*i+3] * (1.0f + erff(h[4*i+3] * 0.7071067811865476f));
                float4 wa = *(const float4*)&S[W2T_OFF + 0 * 132 + c0 + 4 * i];
                float4 wb = *(const float4*)&S[W2T_OFF + 1 * 132 + c0 + 4 * i];
                float4 wc4 = *(const float4*)&S[W2T_OFF + 2 * 132 + c0 + 4 * i];
                float4 wd = *(const float4*)&S[W2T_OFF + 3 * 132 + c0 + 4 * i];
                lp0 += g0 * wa.x + g1 * wa.y + g2 * wa.z + g3 * wa.w;
                lp1 += g0 * wb.x + g1 * wb.y + g2 * wb.z + g3 * wb.w;
                lp2 += g0 * wc4.x + g1 * wc4.y + g2 * wc4.z + g3 * wc4.w;
                lp3 += g0 * wd.x + g1 * wd.y + g2 * wd.z + g3 * wd.w;
            }
#pragma unroll
            for (int off = 1; off < 8; off <<= 1) {
                lp0 += __shfl_xor_sync(0xffffffffu, lp0, off);
                lp1 += __shfl_xor_sync(0xffffffffu, lp1, off);
                lp2 += __shfl_xor_sync(0xffffffffu, lp2, off);
                lp3 += __shfl_xor_sync(0xffffffffu, lp3, off);
            }
            if ((tid & 7) == 0) {
                int hh = rg & (HH - 1);
                float t = fminf(fmaxf(temp[hh], 0.2f), 10.0f);
                float invt = 1.0f / t;
                float q0 = (lp0 + b2[0]) * invt;
                float q1 = (lp1 + b2[1]) * invt;
                float q2 = (lp2 + b2[2]) * invt;
                float q3 = (lp3 + b2[3]) * invt;
                float m = fmaxf(fmaxf(q0, q1), fmaxf(q2, q3));
                float e0 = expf(q0 - m), e1 = expf(q1 - m);
                float e2 = expf(q2 - m), e3 = expf(q3 - m);
                float inv = 1.0f / (e0 + e1 + e2 + e3);
                float w0 = e0 * inv, w1 = e1 * inv, w2v = e2 * inv, w3 = e3 * inv;
                const float* ef = eps_floor + hh * 4;
                w0 = fmaxf(w0, fminf(fmaxf(ef[0], 1e-7f), 0.1f));
                w1 = fmaxf(w1, fminf(fmaxf(ef[1], 1e-7f), 0.1f));
                w2v = fmaxf(w2v, fminf(fmaxf(ef[2], 1e-7f), 0.1f));
                w3 = fmaxf(w3, fminf(fmaxf(ef[3], 1e-7f), 0.1f));
                float inv2 = 1.0f / (w0 + w1 + w2v + w3);
                *(float4*)&out[(size_t)rg * 4] =
                    make_float4(w0 * inv2, w1 * inv2, w2v * inv2, w3 * inv2);
            }
        }
    }
}

// ============================================================================
// Launch
// ============================================================================
extern "C" void kernel_launch(void* const* d_in, const int* in_sizes, int n_in,
                              void* d_out, int out_size)
{
    const float* hidden = (const float*)d_in[0];
    const float* br0    = (const float*)d_in[1];
    const float* br1    = (const float*)d_in[2];
    const float* br2    = (const float*)d_in[3];
    const float* br3    = (const float*)d_in[4];
    const float* W1     = (const float*)d_in[5];
    const float* b1     = (const float*)d_in[6];
    const float* W2     = (const float*)d_in[7];
    const float* b2     = (const float*)d_in[8];
    const float* eps    = (const float*)d_in[9];
    const float* temp   = (const float*)d_in[10];
    float* out = (float*)d_out;

    cudaFuncSetAttribute(pre_kernel, cudaFuncAttributeMaxDynamicSharedMemorySize,
                         PRE_SMEM_FLOATS * 4);
    cudaFuncSetAttribute(main_kernel, cudaFuncAttributeMaxDynamicSharedMemorySize,
                         SM_FLOATS * 4);

    pre_kernel<<<268, 256, PRE_SMEM_FLOATS * 4>>>(hidden, W1, b1);
    main_kernel<<<148, 512, SM_FLOATS * 4>>>(br0, br1, br2, br3, W1, W2,
                                             b2, eps, temp, out);
}

// round 10
// speedup vs baseline: 2.2701x; 1.1722x over previous
#include <cuda_runtime.h>
#include <math.h>
#include <stdint.h>

#define HH    16
#define NROWS 65536
#define NBL   4096

__device__ float g_wsum[12 * 128];
__device__ float g_hidpart[NBL * 128];   // hidden @ W1[0:1024] + b1

// ---- packed fp32x2 helpers (pre_kernel) ----
__device__ __forceinline__ void ffma2(unsigned long long& d,
                                      unsigned long long a,
                                      unsigned long long b) {
    asm("fma.rn.f32x2 %0, %1, %2, %0;" : "+l"(d) : "l"(a), "l"(b));
}
__device__ __forceinline__ unsigned long long addf32x2(unsigned long long a,
                                                       unsigned long long b) {
    unsigned long long r;
    asm("add.rn.f32x2 %0, %1, %2;" : "=l"(r) : "l"(a), "l"(b));
    return r;
}
__device__ __forceinline__ unsigned long long pack2s(float x) {
    unsigned long long r;
    asm("mov.b64 %0, {%1, %1};" : "=l"(r) : "f"(x));
    return r;
}

// ---- tf32 helpers ----
__device__ __forceinline__ unsigned int tf32c(float x) {
    unsigned int r;
    asm("cvt.rna.tf32.f32 %0, %1;" : "=r"(r) : "f"(x));
    return r;
}
__device__ __forceinline__ void mma_tf32(float* d, const unsigned int* a,
                                         const unsigned int* b) {
    asm("mma.sync.aligned.m16n8k8.row.col.f32.tf32.tf32.f32 "
        "{%0,%1,%2,%3}, {%4,%5,%6,%7}, {%8,%9}, {%0,%1,%2,%3};"
        : "+f"(d[0]), "+f"(d[1]), "+f"(d[2]), "+f"(d[3])
        : "r"(a[0]), "r"(a[1]), "r"(a[2]), "r"(a[3]), "r"(b[0]), "r"(b[1]));
}

// ============================================================================
// Pre-kernel (unchanged from R8): hidden GEMM + wsum
// ============================================================================
#define PRE_A_HALF (32 * 68)
#define PRE_B_HALF (64 * 64)
#define PRE_SMEM_FLOATS (2 * PRE_A_HALF + 2 * PRE_B_HALF)

__global__ __launch_bounds__(256) void pre_kernel(
    const float* __restrict__ hidden,
    const float* __restrict__ W1,
    const float* __restrict__ b1)
{
    if (blockIdx.x >= 256) {
        int ps = blockIdx.x - 256;
        if (threadIdx.x < 128) {
            int j = threadIdx.x;
            int base = 1024 + ps * 64;
            float s = 0.f;
#pragma unroll
            for (int d = 0; d < 64; d++) s += W1[(base + d) * 128 + j];
            g_wsum[ps * 128 + j] = s;
        }
        return;
    }

    extern __shared__ float sm[];
    float* As = sm;
    float* Bs = sm + 2 * PRE_A_HALF;
    float* pbuf = sm;

    int tid = threadIdx.x;
    int l = tid & 31, w = tid >> 5;
    int kh = w >> 1, wr = w & 1;
    int rowg = l >> 3, colg = l & 7;

    unsigned long long acc[4][2][2];
#pragma unroll
    for (int j = 0; j < 4; j++)
#pragma unroll
        for (int q = 0; q < 2; q++) { acc[j][q][0] = 0ull; acc[j][q][1] = 0ull; }

    int m0 = (blockIdx.x >> 1) * 32;
    int c0 = (blockIdx.x & 1) * 64;

    for (int t = 0; t < 8; t++) {
        __syncthreads();
#pragma unroll
        for (int h = 0; h < 2; h++) {
            int kbase = t * 128 + h * 64;
#pragma unroll
            for (int it = 0; it < 2; it++) {
                int idx = tid + it * 256;
                int r = idx >> 4, k4 = (idx & 15) * 4;
                *(float4*)&As[h * PRE_A_HALF + r * 68 + k4] =
                    *(const float4*)&hidden[(size_t)(m0 + r) * 1024 + kbase + k4];
            }
#pragma unroll
            for (int it = 0; it < 4; it++) {
                int idx = tid + it * 256;
                int k = idx >> 4, c4 = (idx & 15) * 4;
                *(float4*)&Bs[h * PRE_B_HALF + k * 64 + c4] =
                    *(const float4*)&W1[(size_t)(kbase + k) * 128 + c0 + c4];
            }
        }
        __syncthreads();
        int half = kh >> 1, sub = kh & 1;
        const float* Ah = &As[half * PRE_A_HALF + (wr * 16 + rowg) * 68 + sub * 32];
        const float* Bh = &Bs[half * PRE_B_HALF + sub * 32 * 64 + colg * 4];
#pragma unroll 4
        for (int kk = 0; kk < 32; kk++) {
            ulonglong2 w0 = *(const ulonglong2*)(Bh + kk * 64);
            ulonglong2 w1 = *(const ulonglong2*)(Bh + kk * 64 + 32);
#pragma unroll
            for (int j = 0; j < 4; j++) {
                unsigned long long xd = pack2s(Ah[j * 4 * 68 + kk]);
                ffma2(acc[j][0][0], xd, w0.x); ffma2(acc[j][0][1], xd, w0.y);
                ffma2(acc[j][1][0], xd, w1.x); ffma2(acc[j][1][1], xd, w1.y);
            }
        }
    }
    __syncthreads();
    if (kh & 1) {
        int part = kh >> 1;
#pragma unroll
        for (int j = 0; j < 4; j++) {
            int r = wr * 16 + rowg + 4 * j;
#pragma unroll
            for (int q = 0; q < 2; q++)
#pragma unroll
                for (int p = 0; p < 2; p++)
                    *(unsigned long long*)&pbuf[part * 2176 + r * 68 + colg * 4 + q * 32 + 2 * p] =
                        acc[j][q][p];
        }
    }
    __syncthreads();
    if (!(kh & 1)) {
        int part = kh >> 1;
#pragma unroll
        for (int j = 0; j < 4; j++) {
            int r = wr * 16 + rowg + 4 * j;
#pragma unroll
            for (int q = 0; q < 2; q++)
#pragma unroll
                for (int p = 0; p < 2; p++) {
                    unsigned long long* a =
                        (unsigned long long*)&pbuf[part * 2176 + r * 68 + colg * 4 + q * 32 + 2 * p];
                    *a = addf32x2(*a, acc[j][q][p]);
                }
        }
    }
    __syncthreads();
#pragma unroll
    for (int it = 0; it < 2; it++) {
        int idx = tid + it * 256;
        int r = idx >> 4, c4 = (idx & 15) * 4;
        float4 h0 = *(const float4*)&pbuf[r * 68 + c4];
        float4 h1 = *(const float4*)&pbuf[2176 + r * 68 + c4];
        float4 bv = *(const float4*)&b1[c0 + c4];
        float4 o = make_float4(h0.x + h1.x + bv.x, h0.y + h1.y + bv.y,
                               h0.z + h1.z + bv.z, h0.w + h1.w + bv.w);
        *(float4*)&g_hidpart[(size_t)(m0 + r) * 128 + c0 + c4] = o;
    }
}

// ============================================================================
// Main kernel: tf32 tensor-core branch GEMM.
// 16 warps = rw(4: 16-row groups) x cw(4: 32-col groups). Warp: m16 x (4 x n8),
// k=256 as 32 k-steps of 8. W pre-permuted into B-fragment order (resident).
// x loaded per tile directly into A-fragment order (tf32). Stats from gmem.
// ============================================================================
#define WF_OFF   0              // W frags: [cw][kt][nt][lane][2] = 32768 floats
#define AF_OFF   32768          // A frags: [rw][kt][lane][4] = 16384 floats
#define HB_OFF   32768          // epilogue h staging (aliases Af), [64][132]
#define HB_PITCH 132
#define ST_OFF   49152          // stat: [12][68]
#define WS_OFF   49968          // wsum: [12][128]
#define W2T_OFF  51504          // w2T:  [4][132]
#define SM_FLOATS 52032         // 208128 B

__global__ __launch_bounds__(512, 1) void main_kernel(
    const float* __restrict__ br0, const float* __restrict__ br1,
    const float* __restrict__ br2, const float* __restrict__ br3,
    const float* __restrict__ W1, const float* __restrict__ W2,
    const float* __restrict__ b2, const float* __restrict__ eps_floor,
    const float* __restrict__ temp, float* __restrict__ out)
{
    extern __shared__ float S[];
    int tid = threadIdx.x;
    int l = tid & 31, w = tid >> 5;
    int rw = w >> 2, cw = w & 3;

    // ---- one-time: W -> B-fragment layout (tf32), wsum, w2T ----
    for (int i = tid; i < 256 * 128; i += 512) {
        int k = i >> 7, c = i & 127;
        float v = W1[(size_t)(1792 + k) * 128 + c];
        int cwi = c >> 5, nt = (c >> 3) & 3, nl = c & 7;
        int kt = k >> 3;
        int lane = nl * 4 + (k & 3);
        int slot = (k >> 2) & 1;
        S[WF_OFF + (((cwi * 32 + kt) * 4 + nt) * 32 + lane) * 2 + slot] =
            __uint_as_float(tf32c(v));
    }
    for (int i = tid; i < 12 * 128; i += 512) S[WS_OFF + i] = g_wsum[i];
    { int c = tid >> 2, n = tid & 3; S[W2T_OFF + n * 132 + c] = W2[c * 4 + n]; }

    const int ntiles = NROWS / 64;   // 1024
    for (int tile = blockIdx.x; tile < ntiles; tile += gridDim.x) {
        int rg0 = tile * 64;
        __syncthreads();   // prev epilogue HB/ST reads done; one-time init on iter 0

        // ---- x -> A-fragment layout (tf32) ----
#pragma unroll
        for (int p = 0; p < 4; p++) {
            const float* bp = (p == 0) ? br0 : (p == 1) ? br1 : (p == 2) ? br2 : br3;
            const float4* bp4 = (const float4*)bp + (size_t)rg0 * 16;
#pragma unroll
            for (int it = 0; it < 2; it++) {
                int idx = tid + it * 512;
                int r = idx >> 4, d4 = (idx & 15) * 4;
                float4 v = bp4[idx];
                int kt = p * 8 + (d4 >> 3);
                int slot = ((r >> 3) & 1) + ((d4 >> 2) & 1) * 2;
                int base = AF_OFF + (((r >> 4) * 32 + kt) * 32 + (r & 7) * 4) * 4 + slot;
                S[base + 0]  = __uint_as_float(tf32c(v.x));
                S[base + 4]  = __uint_as_float(tf32c(v.y));
                S[base + 8]  = __uint_as_float(tf32c(v.z));
                S[base + 12] = __uint_as_float(tf32c(v.w));
            }
        }
        __syncthreads();

        // ---- stats from gmem (L2-hot), warps 0-7 ----
        if (tid < 256) {
            int r = tid & 63, p = tid >> 6;
            const float* bp = (p == 0) ? br0 : (p == 1) ? br1 : (p == 2) ? br2 : br3;
            const float4* xp = (const float4*)(bp + (size_t)(rg0 + r) * 64);
            float sum = 0.f, sq = 0.f, mx = -INFINITY;
#pragma unroll
            for (int i = 0; i < 16; i++) {
                float4 v = xp[i];
                sum += v.x + v.y + v.z + v.w;
                sq += v.x * v.x + v.y * v.y + v.z * v.z + v.w * v.w;
                mx = fmaxf(mx, fmaxf(fmaxf(v.x, v.y), fmaxf(v.z, v.w)));
            }
            S[ST_OFF + (p * 3 + 0) * 68 + r] = sum * (1.0f / 64.0f);
            S[ST_OFF + (p * 3 + 1) * 68 + r] = sqrtf(fmaxf(sq * (1.0f / 64.0f), 1e-8f));
            S[ST_OFF + (p * 3 + 2) * 68 + r] = mx;
        }

        // ---- tensor-core GEMM: warp m16 x n32, k=256 ----
        float acc[4][4];
#pragma unroll
        for (int nt = 0; nt < 4; nt++)
#pragma unroll
            for (int i = 0; i < 4; i++) acc[nt][i] = 0.f;
        {
            const float* afp = &S[AF_OFF + rw * 32 * 128 + l * 4];
            const float* wfp = &S[WF_OFF + cw * 32 * 256 + l * 2];
#pragma unroll 8
            for (int kt = 0; kt < 32; kt++) {
                float4 av = *(const float4*)(afp + kt * 128);
                unsigned int a[4] = {__float_as_uint(av.x), __float_as_uint(av.y),
                                     __float_as_uint(av.z), __float_as_uint(av.w)};
#pragma unroll
                for (int nt = 0; nt < 4; nt++) {
                    float2 bv = *(const float2*)(wfp + kt * 256 + nt * 64);
                    unsigned int b[2] = {__float_as_uint(bv.x), __float_as_uint(bv.y)};
                    mma_tf32(acc[nt], a, b);
                }
            }
        }
        __syncthreads();   // all Af reads done -> HB may overwrite

        // ---- C fragments -> HB rows ----
        {
            int row0 = rw * 16 + (l >> 2);
            int colb = cw * 32 + (l & 3) * 2;
#pragma unroll
            for (int nt = 0; nt < 4; nt++) {
                *(float2*)&S[HB_OFF + row0 * HB_PITCH + colb + nt * 8] =
                    make_float2(acc[nt][0], acc[nt][1]);
                *(float2*)&S[HB_OFF + (row0 + 8) * HB_PITCH + colb + nt * 8] =
                    make_float2(acc[nt][2], acc[nt][3]);
            }
        }
        __syncthreads();

        // ---- epilogue: thread = (row r, 16-col chunk) ----
        {
            int r = tid >> 3;
            int c0 = (tid & 7) * 16;
            int rg = rg0 + r;
            float h[16];
#pragma unroll
            for (int i = 0; i < 4; i++) {
                float4 a = *(const float4*)&S[HB_OFF + r * HB_PITCH + c0 + 4 * i];
                float4 v = *(const float4*)&g_hidpart[(size_t)(rg >> 4) * 128 + c0 + 4 * i];
                h[4 * i + 0] = a.x + v.x;
                h[4 * i + 1] = a.y + v.y;
                h[4 * i + 2] = a.z + v.z;
                h[4 * i + 3] = a.w + v.w;
            }
#pragma unroll
            for (int ps = 0; ps < 12; ps++) {
                float sv = S[ST_OFF + ps * 68 + r];
#pragma unroll
                for (int i = 0; i < 4; i++) {
                    float4 wv = *(const float4*)&S[WS_OFF + ps * 128 + c0 + 4 * i];
                    h[4 * i + 0] += sv * wv.x; h[4 * i + 1] += sv * wv.y;
                    h[4 * i + 2] += sv * wv.z; h[4 * i + 3] += sv * wv.w;
                }
            }
            float lp0 = 0.f, lp1 = 0.f, lp2 = 0.f, lp3 = 0.f;
#pragma unroll
            for (int i = 0; i < 4; i++) {
                float g0 = 0.5f * h[4*i+0] * (1.0f + erff(h[4*i+0] * 0.7071067811865476f));
                float g1 = 0.5f * h[4*i+1] * (1.0f + erff(h[4*i+1] * 0.7071067811865476f));
                float g2 = 0.5f * h[4*i+2] * (1.0f + erff(h[4*i+2] * 0.7071067811865476f));
                float g3 = 0.5f * h[4*i+3] * (1.0f + erff(h[4*i+3] * 0.7071067811865476f));
                float4 wa = *(const float4*)&S[W2T_OFF + 0 * 132 + c0 + 4 * i];
                float4 wb = *(const float4*)&S[W2T_OFF + 1 * 132 + c0 + 4 * i];
                float4 wc4 = *(const float4*)&S[W2T_OFF + 2 * 132 + c0 + 4 * i];
                float4 wd = *(const float4*)&S[W2T_OFF + 3 * 132 + c0 + 4 * i];
                lp0 += g0 * wa.x + g1 * wa.y + g2 * wa.z + g3 * wa.w;
                lp1 += g0 * wb.x + g1 * wb.y + g2 * wb.z + g3 * wb.w;
                lp2 += g0 * wc4.x + g1 * wc4.y + g2 * wc4.z + g3 * wc4.w;
                lp3 += g0 * wd.x + g1 * wd.y + g2 * wd.z + g3 * wd.w;
            }
#pragma unroll
            for (int off = 1; off < 8; off <<= 1) {
                lp0 += __shfl_xor_sync(0xffffffffu, lp0, off);
                lp1 += __shfl_xor_sync(0xffffffffu, lp1, off);
                lp2 += __shfl_xor_sync(0xffffffffu, lp2, off);
                lp3 += __shfl_xor_sync(0xffffffffu, lp3, off);
            }
            if ((tid & 7) == 0) {
                int hh = rg & (HH - 1);
                float t = fminf(fmaxf(temp[hh], 0.2f), 10.0f);
                float invt = 1.0f / t;
                float q0 = (lp0 + b2[0]) * invt;
                float q1 = (lp1 + b2[1]) * invt;
                float q2 = (lp2 + b2[2]) * invt;
                float q3 = (lp3 + b2[3]) * invt;
                float m = fmaxf(fmaxf(q0, q1), fmaxf(q2, q3));
                float e0 = expf(q0 - m), e1 = expf(q1 - m);
                float e2 = expf(q2 - m), e3 = expf(q3 - m);
                float inv = 1.0f / (e0 + e1 + e2 + e3);
                float w0 = e0 * inv, w1 = e1 * inv, w2v = e2 * inv, w3 = e3 * inv;
                const float* ef = eps_floor + hh * 4;
                w0 = fmaxf(w0, fminf(fmaxf(ef[0], 1e-7f), 0.1f));
                w1 = fmaxf(w1, fminf(fmaxf(ef[1], 1e-7f), 0.1f));
                w2v = fmaxf(w2v, fminf(fmaxf(ef[2], 1e-7f), 0.1f));
                w3 = fmaxf(w3, fminf(fmaxf(ef[3], 1e-7f), 0.1f));
                float inv2 = 1.0f / (w0 + w1 + w2v + w3);
                *(float4*)&out[(size_t)rg * 4] =
                    make_float4(w0 * inv2, w1 * inv2, w2v * inv2, w3 * inv2);
            }
        }
    }
}

// ============================================================================
// Launch
// ============================================================================
extern "C" void kernel_launch(void* const* d_in, const int* in_sizes, int n_in,
                              void* d_out, int out_size)
{
    const float* hidden = (const float*)d_in[0];
    const float* br0    = (const float*)d_in[1];
    const float* br1    = (const float*)d_in[2];
    const float* br2    = (const float*)d_in[3];
    const float* br3    = (const float*)d_in[4];
    const float* W1     = (const float*)d_in[5];
    const float* b1     = (const float*)d_in[6];
    const float* W2     = (const float*)d_in[7];
    const float* b2     = (const float*)d_in[8];
    const float* eps    = (const float*)d_in[9];
    const float* temp   = (const float*)d_in[10];
    float* out = (float*)d_out;

    cudaFuncSetAttribute(pre_kernel, cudaFuncAttributeMaxDynamicSharedMemorySize,
                         PRE_SMEM_FLOATS * 4);
    cudaFuncSetAttribute(main_kernel, cudaFuncAttributeMaxDynamicSharedMemorySize,
                         SM_FLOATS * 4);

    pre_kernel<<<268, 256, PRE_SMEM_FLOATS * 4>>>(hidden, W1, b1);
    main_kernel<<<148, 512, SM_FLOATS * 4>>>(br0, br1, br2, br3, W1, W2,
                                             b2, eps, temp, out);
}

// round 11
// speedup vs baseline: 2.4245x; 1.0680x over previous
#include <cuda_runtime.h>
#include <cuda_fp16.h>
#include <math.h>
#include <stdint.h>

#define HH    16
#define NROWS 65536
#define NBL   4096

__device__ float g_wsum[12 * 128];
__device__ float g_hidpart[NBL * 128];   // hidden @ W1[0:1024] + b1

// ---- packed fp32x2 helpers (pre_kernel) ----
__device__ __forceinline__ void ffma2(unsigned long long& d,
                                      unsigned long long a,
                                      unsigned long long b) {
    asm("fma.rn.f32x2 %0, %1, %2, %0;" : "+l"(d) : "l"(a), "l"(b));
}
__device__ __forceinline__ unsigned long long addf32x2(unsigned long long a,
                                                       unsigned long long b) {
    unsigned long long r;
    asm("add.rn.f32x2 %0, %1, %2;" : "=l"(r) : "l"(a), "l"(b));
    return r;
}
__device__ __forceinline__ unsigned long long pack2s(float x) {
    unsigned long long r;
    asm("mov.b64 %0, {%1, %1};" : "=l"(r) : "f"(x));
    return r;
}

// ---- fp16 mma ----
__device__ __forceinline__ void mma_fp16(float* d, const unsigned int* a,
                                         unsigned int b0, unsigned int b1) {
    asm("mma.sync.aligned.m16n8k16.row.col.f32.f16.f16.f32 "
        "{%0,%1,%2,%3}, {%4,%5,%6,%7}, {%8,%9}, {%0,%1,%2,%3};"
        : "+f"(d[0]), "+f"(d[1]), "+f"(d[2]), "+f"(d[3])
        : "r"(a[0]), "r"(a[1]), "r"(a[2]), "r"(a[3]), "r"(b0), "r"(b1));
}

// ============================================================================
// Pre-kernel (unchanged): hidden GEMM + wsum
// ============================================================================
#define PRE_A_HALF (32 * 68)
#define PRE_B_HALF (64 * 64)
#define PRE_SMEM_FLOATS (2 * PRE_A_HALF + 2 * PRE_B_HALF)

__global__ __launch_bounds__(256) void pre_kernel(
    const float* __restrict__ hidden,
    const float* __restrict__ W1,
    const float* __restrict__ b1)
{
    if (blockIdx.x >= 256) {
        int ps = blockIdx.x - 256;
        if (threadIdx.x < 128) {
            int j = threadIdx.x;
            int base = 1024 + ps * 64;
            float s = 0.f;
#pragma unroll
            for (int d = 0; d < 64; d++) s += W1[(base + d) * 128 + j];
            g_wsum[ps * 128 + j] = s;
        }
        return;
    }

    extern __shared__ float sm[];
    float* As = sm;
    float* Bs = sm + 2 * PRE_A_HALF;
    float* pbuf = sm;

    int tid = threadIdx.x;
    int l = tid & 31, w = tid >> 5;
    int kh = w >> 1, wr = w & 1;
    int rowg = l >> 3, colg = l & 7;

    unsigned long long acc[4][2][2];
#pragma unroll
    for (int j = 0; j < 4; j++)
#pragma unroll
        for (int q = 0; q < 2; q++) { acc[j][q][0] = 0ull; acc[j][q][1] = 0ull; }

    int m0 = (blockIdx.x >> 1) * 32;
    int c0 = (blockIdx.x & 1) * 64;

    for (int t = 0; t < 8; t++) {
        __syncthreads();
#pragma unroll
        for (int h = 0; h < 2; h++) {
            int kbase = t * 128 + h * 64;
#pragma unroll
            for (int it = 0; it < 2; it++) {
                int idx = tid + it * 256;
                int r = idx >> 4, k4 = (idx & 15) * 4;
                *(float4*)&As[h * PRE_A_HALF + r * 68 + k4] =
                    *(const float4*)&hidden[(size_t)(m0 + r) * 1024 + kbase + k4];
            }
#pragma unroll
            for (int it = 0; it < 4; it++) {
                int idx = tid + it * 256;
                int k = idx >> 4, c4 = (idx & 15) * 4;
                *(float4*)&Bs[h * PRE_B_HALF + k * 64 + c4] =
                    *(const float4*)&W1[(size_t)(kbase + k) * 128 + c0 + c4];
            }
        }
        __syncthreads();
        int half = kh >> 1, sub = kh & 1;
        const float* Ah = &As[half * PRE_A_HALF + (wr * 16 + rowg) * 68 + sub * 32];
        const float* Bh = &Bs[half * PRE_B_HALF + sub * 32 * 64 + colg * 4];
#pragma unroll 4
        for (int kk = 0; kk < 32; kk++) {
            ulonglong2 w0 = *(const ulonglong2*)(Bh + kk * 64);
            ulonglong2 w1 = *(const ulonglong2*)(Bh + kk * 64 + 32);
#pragma unroll
            for (int j = 0; j < 4; j++) {
                unsigned long long xd = pack2s(Ah[j * 4 * 68 + kk]);
                ffma2(acc[j][0][0], xd, w0.x); ffma2(acc[j][0][1], xd, w0.y);
                ffma2(acc[j][1][0], xd, w1.x); ffma2(acc[j][1][1], xd, w1.y);
            }
        }
    }
    __syncthreads();
    if (kh & 1) {
        int part = kh >> 1;
#pragma unroll
        for (int j = 0; j < 4; j++) {
            int r = wr * 16 + rowg + 4 * j;
#pragma unroll
            for (int q = 0; q < 2; q++)
#pragma unroll
                for (int p = 0; p < 2; p++)
                    *(unsigned long long*)&pbuf[part * 2176 + r * 68 + colg * 4 + q * 32 + 2 * p] =
                        acc[j][q][p];
        }
    }
    __syncthreads();
    if (!(kh & 1)) {
        int part = kh >> 1;
#pragma unroll
        for (int j = 0; j < 4; j++) {
            int r = wr * 16 + rowg + 4 * j;
#pragma unroll
            for (int q = 0; q < 2; q++)
#pragma unroll
                for (int p = 0; p < 2; p++) {
                    unsigned long long* a =
                        (unsigned long long*)&pbuf[part * 2176 + r * 68 + colg * 4 + q * 32 + 2 * p];
                    *a = addf32x2(*a, acc[j][q][p]);
                }
        }
    }
    __syncthreads();
#pragma unroll
    for (int it = 0; it < 2; it++) {
        int idx = tid + it * 256;
        int r = idx >> 4, c4 = (idx & 15) * 4;
        float4 h0 = *(const float4*)&pbuf[r * 68 + c4];
        float4 h1 = *(const float4*)&pbuf[2176 + r * 68 + c4];
        float4 bv = *(const float4*)&b1[c0 + c4];
        float4 o = make_float4(h0.x + h1.x + bv.x, h0.y + h1.y + bv.y,
                               h0.z + h1.z + bv.z, h0.w + h1.w + bv.w);
        *(float4*)&g_hidpart[(size_t)(m0 + r) * 128 + c0 + c4] = o;
    }
}

// ============================================================================
// Main kernel: fp16 tensor-core branch GEMM. TM=128 rows/tile (512 tiles).
// 16 warps = rw(4: 32-row) x cw(4: 32-col). Warp: m32 x n32 x k256 (16 ksteps).
// x stored as packed half2 row-major (pitch 132 words -> conflict-free A LDS.32).
// W pre-permuted into dense per-lane B-fragment float4s (one-time).
// ============================================================================
#define WFA_OFF  0              // [4 cw][16 kt][32 lane][4 words]  (nt 0,1)
#define WFB_OFF  8192           // same (nt 2,3)
#define X2_OFF   16384          // x half2: [128][132] words; HB fp32 aliases
#define X2_PITCH 132
#define ST_OFF   33280          // stat: [12][132]
#define WS_OFF   34864          // wsum: [12][128]
#define W2T_OFF  36400          // w2T:  [4][132]
#define SM_FLOATS 36928         // 147712 B

__global__ __launch_bounds__(512, 1) void main_kernel(
    const float* __restrict__ br0, const float* __restrict__ br1,
    const float* __restrict__ br2, const float* __restrict__ br3,
    const float* __restrict__ W1, const float* __restrict__ W2,
    const float* __restrict__ b2, const float* __restrict__ eps_floor,
    const float* __restrict__ temp, float* __restrict__ out)
{
    extern __shared__ float S[];
    unsigned int* US = (unsigned int*)S;
    int tid = threadIdx.x;
    int l = tid & 31, w = tid >> 5;
    int rw = w >> 2, cw = w & 3;

    // ---- one-time: W -> fp16 B-fragment layout, wsum, w2T ----
    for (int i = tid; i < 128 * 128; i += 512) {
        int k2 = i >> 7, n = i & 127;
        int k = 2 * k2;
        __half2 hv = __floats2half2_rn(W1[(size_t)(1792 + k) * 128 + n],
                                       W1[(size_t)(1793 + k) * 128 + n]);
        int kt = k2 >> 3, kk = k2 & 7;
        int b = kk >> 2, lk = kk & 3;
        int cwi = n >> 5, nn = n & 31;
        int nt = nn >> 3, lhi = nn & 7;
        int lane = lhi * 4 + lk;
        int base = (nt >> 1) ? WFB_OFF : WFA_OFF;
        int widx = (nt & 1) * 2 + b;
        US[base + ((cwi * 16 + kt) * 32 + lane) * 4 + widx] =
            *(unsigned int*)&hv;
    }
    for (int i = tid; i < 12 * 128; i += 512) S[WS_OFF + i] = g_wsum[i];
    { int c = tid >> 2, n = tid & 3; S[W2T_OFF + n * 132 + c] = W2[c * 4 + n]; }

    const int ntiles = NROWS / 128;   // 512
    for (int tile = blockIdx.x; tile < ntiles; tile += gridDim.x) {
        int rg0 = tile * 128;
        __syncthreads();   // prev epilogue done (HB/ST reads); one-time init iter 0

        // ---- x -> half2 row-major smem ----
#pragma unroll
        for (int p = 0; p < 4; p++) {
            const float* bp = (p == 0) ? br0 : (p == 1) ? br1 : (p == 2) ? br2 : br3;
            const float4* bp4 = (const float4*)bp + (size_t)rg0 * 16;
#pragma unroll
            for (int it = 0; it < 4; it++) {
                int idx = tid + it * 512;
                int r = idx >> 4, d4 = (idx & 15) * 4;
                float4 v = bp4[idx];
                __half2 h0 = __floats2half2_rn(v.x, v.y);
                __half2 h1 = __floats2half2_rn(v.z, v.w);
                int c2 = p * 32 + (d4 >> 1);
                *(uint2*)&US[X2_OFF + r * X2_PITCH + c2] =
                    make_uint2(*(unsigned int*)&h0, *(unsigned int*)&h1);
            }
        }

        // ---- stats from gmem (fp32 precision; L2-hot) ----
        {
            int r = tid & 127, p = tid >> 7;
            const float* bp = (p == 0) ? br0 : (p == 1) ? br1 : (p == 2) ? br2 : br3;
            const float4* xp = (const float4*)(bp + (size_t)(rg0 + r) * 64);
            float sum = 0.f, sq = 0.f, mx = -INFINITY;
#pragma unroll
            for (int i = 0; i < 16; i++) {
                float4 v = xp[i];
                sum += v.x + v.y + v.z + v.w;
                sq += v.x * v.x + v.y * v.y + v.z * v.z + v.w * v.w;
                mx = fmaxf(mx, fmaxf(fmaxf(v.x, v.y), fmaxf(v.z, v.w)));
            }
            S[ST_OFF + (p * 3 + 0) * 132 + r] = sum * (1.0f / 64.0f);
            S[ST_OFF + (p * 3 + 1) * 132 + r] = sqrtf(fmaxf(sq * (1.0f / 64.0f), 1e-8f));
            S[ST_OFF + (p * 3 + 2) * 132 + r] = mx;
        }
        __syncthreads();

        // ---- fp16 tensor GEMM: warp m32 x n32, k=256 ----
        float acc[2][4][4];
#pragma unroll
        for (int mg = 0; mg < 2; mg++)
#pragma unroll
            for (int nt = 0; nt < 4; nt++)
#pragma unroll
                for (int i = 0; i < 4; i++) acc[mg][nt][i] = 0.f;
        {
            const unsigned int* xa0 = &US[X2_OFF + (rw * 32 + (l >> 2)) * X2_PITCH + (l & 3)];
            const unsigned int* wfa = &US[WFA_OFF + ((cw * 16) * 32 + l) * 4];
            const unsigned int* wfb = &US[WFB_OFF + ((cw * 16) * 32 + l) * 4];
#pragma unroll
            for (int kt = 0; kt < 16; kt++) {
                unsigned int a[2][4];
#pragma unroll
                for (int mg = 0; mg < 2; mg++) {
                    const unsigned int* xm = xa0 + mg * 16 * X2_PITCH + kt * 8;
                    a[mg][0] = xm[0];
                    a[mg][1] = xm[8 * X2_PITCH];
                    a[mg][2] = xm[4];
                    a[mg][3] = xm[8 * X2_PITCH + 4];
                }
                uint4 bA = *(const uint4*)&wfa[kt * 128];
                uint4 bB = *(const uint4*)&wfb[kt * 128];
#pragma unroll
                for (int mg = 0; mg < 2; mg++) {
                    mma_fp16(acc[mg][0], a[mg], bA.x, bA.y);
                    mma_fp16(acc[mg][1], a[mg], bA.z, bA.w);
                    mma_fp16(acc[mg][2], a[mg], bB.x, bB.y);
                    mma_fp16(acc[mg][3], a[mg], bB.z, bB.w);
                }
            }
        }
        __syncthreads();   // x reads done -> HB may overwrite x region

        // ---- C fragments -> HB (fp32, aliases x region) ----
        {
            float* HBf = &S[X2_OFF];
            int colb = cw * 32 + (l & 3) * 2;
#pragma unroll
            for (int mg = 0; mg < 2; mg++) {
                int row0 = rw * 32 + mg * 16 + (l >> 2);
#pragma unroll
                for (int nt = 0; nt < 4; nt++) {
                    *(float2*)&HBf[row0 * 132 + colb + nt * 8] =
                        make_float2(acc[mg][nt][0], acc[mg][nt][1]);
                    *(float2*)&HBf[(row0 + 8) * 132 + colb + nt * 8] =
                        make_float2(acc[mg][nt][2], acc[mg][nt][3]);
                }
            }
        }
        __syncthreads();

        // ---- epilogue: 2 passes; thread = (row r, 16-col chunk) ----
        const float* HBf = &S[X2_OFF];
#pragma unroll
        for (int e = 0; e < 2; e++) {
            int r = (tid >> 3) + 64 * e;
            int c0 = (tid & 7) * 16;
            int rg = rg0 + r;
            float h[16];
#pragma unroll
            for (int i = 0; i < 4; i++) {
                float4 a = *(const float4*)&HBf[r * 132 + c0 + 4 * i];
                float4 v = *(const float4*)&g_hidpart[(size_t)(rg >> 4) * 128 + c0 + 4 * i];
                h[4 * i + 0] = a.x + v.x;
                h[4 * i + 1] = a.y + v.y;
                h[4 * i + 2] = a.z + v.z;
                h[4 * i + 3] = a.w + v.w;
            }
#pragma unroll
            for (int ps = 0; ps < 12; ps++) {
                float sv = S[ST_OFF + ps * 132 + r];
#pragma unroll
                for (int i = 0; i < 4; i++) {
                    float4 wv = *(const float4*)&S[WS_OFF + ps * 128 + c0 + 4 * i];
                    h[4 * i + 0] += sv * wv.x; h[4 * i + 1] += sv * wv.y;
                    h[4 * i + 2] += sv * wv.z; h[4 * i + 3] += sv * wv.w;
                }
            }
            float lp0 = 0.f, lp1 = 0.f, lp2 = 0.f, lp3 = 0.f;
#pragma unroll
            for (int i = 0; i < 4; i++) {
                float g0 = 0.5f * h[4*i+0] * (1.0f + erff(h[4*i+0] * 0.7071067811865476f));
                float g1 = 0.5f * h[4*i+1] * (1.0f + erff(h[4*i+1] * 0.7071067811865476f));
                float g2 = 0.5f * h[4*i+2] * (1.0f + erff(h[4*i+2] * 0.7071067811865476f));
                float g3 = 0.5f * h[4*i+3] * (1.0f + erff(h[4*i+3] * 0.7071067811865476f));
                float4 wa = *(const float4*)&S[W2T_OFF + 0 * 132 + c0 + 4 * i];
                float4 wb = *(const float4*)&S[W2T_OFF + 1 * 132 + c0 + 4 * i];
                float4 wc4 = *(const float4*)&S[W2T_OFF + 2 * 132 + c0 + 4 * i];
                float4 wd = *(const float4*)&S[W2T_OFF + 3 * 132 + c0 + 4 * i];
                lp0 += g0 * wa.x + g1 * wa.y + g2 * wa.z + g3 * wa.w;
                lp1 += g0 * wb.x + g1 * wb.y + g2 * wb.z + g3 * wb.w;
                lp2 += g0 * wc4.x + g1 * wc4.y + g2 * wc4.z + g3 * wc4.w;
                lp3 += g0 * wd.x + g1 * wd.y + g2 * wd.z + g3 * wd.w;
            }
#pragma unroll
            for (int off = 1; off < 8; off <<= 1) {
                lp0 += __shfl_xor_sync(0xffffffffu, lp0, off);
                lp1 += __shfl_xor_sync(0xffffffffu, lp1, off);
                lp2 += __shfl_xor_sync(0xffffffffu, lp2, off);
                lp3 += __shfl_xor_sync(0xffffffffu, lp3, off);
            }
            if ((tid & 7) == 0) {
                int hh = rg & (HH - 1);
                float t = fminf(fmaxf(temp[hh], 0.2f), 10.0f);
                float invt = 1.0f / t;
                float q0 = (lp0 + b2[0]) * invt;
                float q1 = (lp1 + b2[1]) * invt;
                float q2 = (lp2 + b2[2]) * invt;
                float q3 = (lp3 + b2[3]) * invt;
                float m = fmaxf(fmaxf(q0, q1), fmaxf(q2, q3));
                float e0 = expf(q0 - m), e1 = expf(q1 - m);
                float e2 = expf(q2 - m), e3 = expf(q3 - m);
                float inv = 1.0f / (e0 + e1 + e2 + e3);
                float w0 = e0 * inv, w1 = e1 * inv, w2v = e2 * inv, w3 = e3 * inv;
                const float* ef = eps_floor + hh * 4;
                w0 = fmaxf(w0, fminf(fmaxf(ef[0], 1e-7f), 0.1f));
                w1 = fmaxf(w1, fminf(fmaxf(ef[1], 1e-7f), 0.1f));
                w2v = fmaxf(w2v, fminf(fmaxf(ef[2], 1e-7f), 0.1f));
                w3 = fmaxf(w3, fminf(fmaxf(ef[3], 1e-7f), 0.1f));
                float inv2 = 1.0f / (w0 + w1 + w2v + w3);
                *(float4*)&out[(size_t)rg * 4] =
                    make_float4(w0 * inv2, w1 * inv2, w2v * inv2, w3 * inv2);
            }
        }
    }
}

// ============================================================================
// Launch
// ============================================================================
extern "C" void kernel_launch(void* const* d_in, const int* in_sizes, int n_in,
                              void* d_out, int out_size)
{
    const float* hidden = (const float*)d_in[0];
    const float* br0    = (const float*)d_in[1];
    const float* br1    = (const float*)d_in[2];
    const float* br2    = (const float*)d_in[3];
    const float* br3    = (const float*)d_in[4];
    const float* W1     = (const float*)d_in[5];
    const float* b1     = (const float*)d_in[6];
    const float* W2     = (const float*)d_in[7];
    const float* b2     = (const float*)d_in[8];
    const float* eps    = (const float*)d_in[9];
    const float* temp   = (const float*)d_in[10];
    float* out = (float*)d_out;

    cudaFuncSetAttribute(pre_kernel, cudaFuncAttributeMaxDynamicSharedMemorySize,
                         PRE_SMEM_FLOATS * 4);
    cudaFuncSetAttribute(main_kernel, cudaFuncAttributeMaxDynamicSharedMemorySize,
                         SM_FLOATS * 4);

    pre_kernel<<<268, 256, PRE_SMEM_FLOATS * 4>>>(hidden, W1, b1);
    main_kernel<<<148, 512, SM_FLOATS * 4>>>(br0, br1, br2, br3, W1, W2,
                                             b2, eps, temp, out);
}

// round 12
// speedup vs baseline: 3.8259x; 1.5780x over previous
#include <cuda_runtime.h>
#include <cuda_fp16.h>
#include <math.h>
#include <stdint.h>

#define HH    16
#define NROWS 65536
#define NBL   4096

__device__ float g_wsum[12 * 128];
__device__ float g_hidpart[NBL * 128];   // hidden @ W1[0:1024] + b1

// ---- packed fp32x2 helpers (pre_kernel) ----
__device__ __forceinline__ void ffma2(unsigned long long& d,
                                      unsigned long long a,
                                      unsigned long long b) {
    asm("fma.rn.f32x2 %0, %1, %2, %0;" : "+l"(d) : "l"(a), "l"(b));
}
__device__ __forceinline__ unsigned long long addf32x2(unsigned long long a,
                                                       unsigned long long b) {
    unsigned long long r;
    asm("add.rn.f32x2 %0, %1, %2;" : "=l"(r) : "l"(a), "l"(b));
    return r;
}
__device__ __forceinline__ unsigned long long pack2s(float x) {
    unsigned long long r;
    asm("mov.b64 %0, {%1, %1};" : "=l"(r) : "f"(x));
    return r;
}

// ---- fp16 mma ----
__device__ __forceinline__ void mma_fp16(float* d, const unsigned int* a,
                                         unsigned int b0, unsigned int b1) {
    asm("mma.sync.aligned.m16n8k16.row.col.f32.f16.f16.f32 "
        "{%0,%1,%2,%3}, {%4,%5,%6,%7}, {%8,%9}, {%0,%1,%2,%3};"
        : "+f"(d[0]), "+f"(d[1]), "+f"(d[2]), "+f"(d[3])
        : "r"(a[0]), "r"(a[1]), "r"(a[2]), "r"(a[3]), "r"(b0), "r"(b1));
}

// ============================================================================
// Pre-kernel (unchanged): hidden GEMM + wsum
// ============================================================================
#define PRE_A_HALF (32 * 68)
#define PRE_B_HALF (64 * 64)
#define PRE_SMEM_FLOATS (2 * PRE_A_HALF + 2 * PRE_B_HALF)

__global__ __launch_bounds__(256) void pre_kernel(
    const float* __restrict__ hidden,
    const float* __restrict__ W1,
    const float* __restrict__ b1)
{
    if (blockIdx.x >= 256) {
        int ps = blockIdx.x - 256;
        if (threadIdx.x < 128) {
            int j = threadIdx.x;
            int base = 1024 + ps * 64;
            float s = 0.f;
#pragma unroll
            for (int d = 0; d < 64; d++) s += W1[(base + d) * 128 + j];
            g_wsum[ps * 128 + j] = s;
        }
        return;
    }

    extern __shared__ float sm[];
    float* As = sm;
    float* Bs = sm + 2 * PRE_A_HALF;
    float* pbuf = sm;

    int tid = threadIdx.x;
    int l = tid & 31, w = tid >> 5;
    int kh = w >> 1, wr = w & 1;
    int rowg = l >> 3, colg = l & 7;

    unsigned long long acc[4][2][2];
#pragma unroll
    for (int j = 0; j < 4; j++)
#pragma unroll
        for (int q = 0; q < 2; q++) { acc[j][q][0] = 0ull; acc[j][q][1] = 0ull; }

    int m0 = (blockIdx.x >> 1) * 32;
    int c0 = (blockIdx.x & 1) * 64;

    for (int t = 0; t < 8; t++) {
        __syncthreads();
#pragma unroll
        for (int h = 0; h < 2; h++) {
            int kbase = t * 128 + h * 64;
#pragma unroll
            for (int it = 0; it < 2; it++) {
                int idx = tid + it * 256;
                int r = idx >> 4, k4 = (idx & 15) * 4;
                *(float4*)&As[h * PRE_A_HALF + r * 68 + k4] =
                    *(const float4*)&hidden[(size_t)(m0 + r) * 1024 + kbase + k4];
            }
#pragma unroll
            for (int it = 0; it < 4; it++) {
                int idx = tid + it * 256;
                int k = idx >> 4, c4 = (idx & 15) * 4;
                *(float4*)&Bs[h * PRE_B_HALF + k * 64 + c4] =
                    *(const float4*)&W1[(size_t)(kbase + k) * 128 + c0 + c4];
            }
        }
        __syncthreads();
        int half = kh >> 1, sub = kh & 1;
        const float* Ah = &As[half * PRE_A_HALF + (wr * 16 + rowg) * 68 + sub * 32];
        const float* Bh = &Bs[half * PRE_B_HALF + sub * 32 * 64 + colg * 4];
#pragma unroll 4
        for (int kk = 0; kk < 32; kk++) {
            ulonglong2 w0 = *(const ulonglong2*)(Bh + kk * 64);
            ulonglong2 w1 = *(const ulonglong2*)(Bh + kk * 64 + 32);
#pragma unroll
            for (int j = 0; j < 4; j++) {
                unsigned long long xd = pack2s(Ah[j * 4 * 68 + kk]);
                ffma2(acc[j][0][0], xd, w0.x); ffma2(acc[j][0][1], xd, w0.y);
                ffma2(acc[j][1][0], xd, w1.x); ffma2(acc[j][1][1], xd, w1.y);
            }
        }
    }
    __syncthreads();
    if (kh & 1) {
        int part = kh >> 1;
#pragma unroll
        for (int j = 0; j < 4; j++) {
            int r = wr * 16 + rowg + 4 * j;
#pragma unroll
            for (int q = 0; q < 2; q++)
#pragma unroll
                for (int p = 0; p < 2; p++)
                    *(unsigned long long*)&pbuf[part * 2176 + r * 68 + colg * 4 + q * 32 + 2 * p] =
                        acc[j][q][p];
        }
    }
    __syncthreads();
    if (!(kh & 1)) {
        int part = kh >> 1;
#pragma unroll
        for (int j = 0; j < 4; j++) {
            int r = wr * 16 + rowg + 4 * j;
#pragma unroll
            for (int q = 0; q < 2; q++)
#pragma unroll
                for (int p = 0; p < 2; p++) {
                    unsigned long long* a =
                        (unsigned long long*)&pbuf[part * 2176 + r * 68 + colg * 4 + q * 32 + 2 * p];
                    *a = addf32x2(*a, acc[j][q][p]);
                }
        }
    }
    __syncthreads();
#pragma unroll
    for (int it = 0; it < 2; it++) {
        int idx = tid + it * 256;
        int r = idx >> 4, c4 = (idx & 15) * 4;
        float4 h0 = *(const float4*)&pbuf[r * 68 + c4];
        float4 h1 = *(const float4*)&pbuf[2176 + r * 68 + c4];
        float4 bv = *(const float4*)&b1[c0 + c4];
        float4 o = make_float4(h0.x + h1.x + bv.x, h0.y + h1.y + bv.y,
                               h0.z + h1.z + bv.z, h0.w + h1.w + bv.w);
        *(float4*)&g_hidpart[(size_t)(m0 + r) * 128 + c0 + c4] = o;
    }
}

// ============================================================================
// Main kernel: fp16 tensor-core GEMM with stats folded in as a 17th k-step.
// TM=128 rows/tile (512 tiles). 16 warps = rw(4) x cw(4), warp m32 x n32.
// x row: 256 branch halves + 12 stat halves + 4 zero pads (k=272 total).
// Stats computed during staging via half-warp shuffle reductions (fp32).
// ============================================================================
#define WFA_OFF  0              // [4 cw][17 kt][32 lane][4 words]  (nt 0,1)
#define WFB_OFF  8704           // same (nt 2,3)
#define X2_OFF   17408          // x half2: [128][140] words; HB fp32 aliases
#define X2_PITCH 140
#define W2T_OFF  35328          // w2T: [4][132]
#define SM_FLOATS 35856         // 143424 B

__global__ __launch_bounds__(512, 1) void main_kernel(
    const float* __restrict__ br0, const float* __restrict__ br1,
    const float* __restrict__ br2, const float* __restrict__ br3,
    const float* __restrict__ W1, const float* __restrict__ W2,
    const float* __restrict__ b2, const float* __restrict__ eps_floor,
    const float* __restrict__ temp, float* __restrict__ out)
{
    extern __shared__ float S[];
    unsigned int* US = (unsigned int*)S;
    int tid = threadIdx.x;
    int l = tid & 31, w = tid >> 5;
    int rw = w >> 2, cw = w & 3;

    // ---- one-time: W rows 1792.. -> fp16 B-fragments (ksteps 0..15) ----
    for (int i = tid; i < 128 * 128; i += 512) {
        int k2 = i >> 7, n = i & 127;
        int k = 2 * k2;
        __half2 hv = __floats2half2_rn(W1[(size_t)(1792 + k) * 128 + n],
                                       W1[(size_t)(1793 + k) * 128 + n]);
        int kt = k2 >> 3, kk = k2 & 7;
        int b = kk >> 2, lk = kk & 3;
        int cwi = n >> 5, nn = n & 31;
        int nt = nn >> 3, lhi = nn & 7;
        int lane = lhi * 4 + lk;
        int base = (nt >> 1) ? WFB_OFF : WFA_OFF;
        int widx = (nt & 1) * 2 + b;
        US[base + ((cwi * 17 + kt) * 32 + lane) * 4 + widx] = *(unsigned int*)&hv;
    }
    // ---- one-time: wsum -> B-fragments for kstep 16 (ps 0..11, pads 0) ----
    for (int i = tid; i < 8 * 128; i += 512) {
        int kk = i >> 7, n = i & 127;
        int ps0 = 2 * kk, ps1 = ps0 + 1;
        float v0 = (ps0 < 12) ? g_wsum[ps0 * 128 + n] : 0.f;
        float v1 = (ps1 < 12) ? g_wsum[ps1 * 128 + n] : 0.f;
        __half2 hv = __floats2half2_rn(v0, v1);
        int b = kk >> 2, lk = kk & 3;
        int cwi = n >> 5, nn = n & 31;
        int nt = nn >> 3, lhi = nn & 7;
        int lane = lhi * 4 + lk;
        int base = (nt >> 1) ? WFB_OFF : WFA_OFF;
        int widx = (nt & 1) * 2 + b;
        US[base + ((cwi * 17 + 16) * 32 + lane) * 4 + widx] = *(unsigned int*)&hv;
    }
    { int c = tid >> 2, n = tid & 3; S[W2T_OFF + n * 132 + c] = W2[c * 4 + n]; }

    const int ntiles = NROWS / 128;   // 512
    for (int tile = blockIdx.x; tile < ntiles; tile += gridDim.x) {
        int rg0 = tile * 128;
        __syncthreads();   // prev epilogue HB reads done; one-time init iter 0

        // ---- x -> half2 smem + stats via half-warp reduction ----
#pragma unroll
        for (int p = 0; p < 4; p++) {
            const float* bp = (p == 0) ? br0 : (p == 1) ? br1 : (p == 2) ? br2 : br3;
            const float4* bp4 = (const float4*)bp + (size_t)rg0 * 16;
#pragma unroll
            for (int it = 0; it < 4; it++) {
                int idx = tid + it * 512;
                int r = idx >> 4, d4 = (idx & 15) * 4;
                float4 v = bp4[idx];
                __half2 h0 = __floats2half2_rn(v.x, v.y);
                __half2 h1 = __floats2half2_rn(v.z, v.w);
                *(uint2*)&US[X2_OFF + r * X2_PITCH + p * 32 + (d4 >> 1)] =
                    make_uint2(*(unsigned int*)&h0, *(unsigned int*)&h1);
                // stats over this (r, p): 16 lanes hold the 64 values
                float sum = v.x + v.y + v.z + v.w;
                float sq = v.x * v.x + v.y * v.y + v.z * v.z + v.w * v.w;
                float mx = fmaxf(fmaxf(v.x, v.y), fmaxf(v.z, v.w));
#pragma unroll
                for (int off = 1; off < 16; off <<= 1) {
                    sum += __shfl_xor_sync(0xffffffffu, sum, off);
                    sq  += __shfl_xor_sync(0xffffffffu, sq, off);
                    mx = fmaxf(mx, __shfl_xor_sync(0xffffffffu, mx, off));
                }
                int sl = l & 15;
                if (sl == 0) {
                    __half* hrow = (__half*)&US[X2_OFF + r * X2_PITCH];
                    hrow[256 + p * 3 + 0] = __float2half_rn(sum * (1.0f / 64.0f));
                    hrow[256 + p * 3 + 1] =
                        __float2half_rn(sqrtf(fmaxf(sq * (1.0f / 64.0f), 1e-8f)));
                    hrow[256 + p * 3 + 2] = __float2half_rn(mx);
                } else if (p == 0 && sl == 1) {
                    *(uint2*)&US[X2_OFF + r * X2_PITCH + 134] = make_uint2(0u, 0u);
                }
            }
        }
        __syncthreads();

        // ---- fp16 tensor GEMM: warp m32 x n32, k=272 (17 ksteps) ----
        float acc[2][4][4];
#pragma unroll
        for (int mg = 0; mg < 2; mg++)
#pragma unroll
            for (int nt = 0; nt < 4; nt++)
#pragma unroll
                for (int i = 0; i < 4; i++) acc[mg][nt][i] = 0.f;
        {
            const unsigned int* xa0 =
                &US[X2_OFF + (rw * 32 + (l >> 2)) * X2_PITCH + (l & 3)];
            const unsigned int* wfa = &US[WFA_OFF + ((cw * 17) * 32 + l) * 4];
            const unsigned int* wfb = &US[WFB_OFF + ((cw * 17) * 32 + l) * 4];
#pragma unroll
            for (int kt = 0; kt < 17; kt++) {
                unsigned int a[2][4];
#pragma unroll
                for (int mg = 0; mg < 2; mg++) {
                    const unsigned int* xm = xa0 + mg * 16 * X2_PITCH + kt * 8;
                    a[mg][0] = xm[0];
                    a[mg][1] = xm[8 * X2_PITCH];
                    a[mg][2] = xm[4];
                    a[mg][3] = xm[8 * X2_PITCH + 4];
                }
                uint4 bA = *(const uint4*)&wfa[kt * 128];
                uint4 bB = *(const uint4*)&wfb[kt * 128];
#pragma unroll
                for (int mg = 0; mg < 2; mg++) {
                    mma_fp16(acc[mg][0], a[mg], bA.x, bA.y);
                    mma_fp16(acc[mg][1], a[mg], bA.z, bA.w);
                    mma_fp16(acc[mg][2], a[mg], bB.x, bB.y);
                    mma_fp16(acc[mg][3], a[mg], bB.z, bB.w);
                }
            }
        }
        __syncthreads();   // x reads done -> HB may overwrite x region

        // ---- C fragments -> HB (fp32, aliases x region, pitch 140) ----
        {
            float* HBf = &S[X2_OFF];
            int colb = cw * 32 + (l & 3) * 2;
#pragma unroll
            for (int mg = 0; mg < 2; mg++) {
                int row0 = rw * 32 + mg * 16 + (l >> 2);
#pragma unroll
                for (int nt = 0; nt < 4; nt++) {
                    *(float2*)&HBf[row0 * X2_PITCH + colb + nt * 8] =
                        make_float2(acc[mg][nt][0], acc[mg][nt][1]);
                    *(float2*)&HBf[(row0 + 8) * X2_PITCH + colb + nt * 8] =
                        make_float2(acc[mg][nt][2], acc[mg][nt][3]);
                }
            }
        }
        __syncthreads();

        // ---- epilogue: 2 passes; thread = (row r, 16-col chunk) ----
        const float* HBf = &S[X2_OFF];
#pragma unroll
        for (int e = 0; e < 2; e++) {
            int r = (tid >> 3) + 64 * e;
            int c0 = (tid & 7) * 16;
            int rg = rg0 + r;
            float h[16];
#pragma unroll
            for (int i = 0; i < 4; i++) {
                float4 a = *(const float4*)&HBf[r * X2_PITCH + c0 + 4 * i];
                float4 v = *(const float4*)&g_hidpart[(size_t)(rg >> 4) * 128 + c0 + 4 * i];
                h[4 * i + 0] = a.x + v.x;
                h[4 * i + 1] = a.y + v.y;
                h[4 * i + 2] = a.z + v.z;
                h[4 * i + 3] = a.w + v.w;
            }
            float lp0 = 0.f, lp1 = 0.f, lp2 = 0.f, lp3 = 0.f;
#pragma unroll
            for (int i = 0; i < 4; i++) {
                float g0 = 0.5f * h[4*i+0] * (1.0f + erff(h[4*i+0] * 0.7071067811865476f));
                float g1 = 0.5f * h[4*i+1] * (1.0f + erff(h[4*i+1] * 0.7071067811865476f));
                float g2 = 0.5f * h[4*i+2] * (1.0f + erff(h[4*i+2] * 0.7071067811865476f));
                float g3 = 0.5f * h[4*i+3] * (1.0f + erff(h[4*i+3] * 0.7071067811865476f));
                float4 wa = *(const float4*)&S[W2T_OFF + 0 * 132 + c0 + 4 * i];
                float4 wb = *(const float4*)&S[W2T_OFF + 1 * 132 + c0 + 4 * i];
                float4 wc4 = *(const float4*)&S[W2T_OFF + 2 * 132 + c0 + 4 * i];
                float4 wd = *(const float4*)&S[W2T_OFF + 3 * 132 + c0 + 4 * i];
                lp0 += g0 * wa.x + g1 * wa.y + g2 * wa.z + g3 * wa.w;
                lp1 += g0 * wb.x + g1 * wb.y + g2 * wb.z + g3 * wb.w;
                lp2 += g0 * wc4.x + g1 * wc4.y + g2 * wc4.z + g3 * wc4.w;
                lp3 += g0 * wd.x + g1 * wd.y + g2 * wd.z + g3 * wd.w;
            }
#pragma unroll
            for (int off = 1; off < 8; off <<= 1) {
                lp0 += __shfl_xor_sync(0xffffffffu, lp0, off);
                lp1 += __shfl_xor_sync(0xffffffffu, lp1, off);
                lp2 += __shfl_xor_sync(0xffffffffu, lp2, off);
                lp3 += __shfl_xor_sync(0xffffffffu, lp3, off);
            }
            if ((tid & 7) == 0) {
                int hh = rg & (HH - 1);
                float t = fminf(fmaxf(temp[hh], 0.2f), 10.0f);
                float invt = 1.0f / t;
                float q0 = (lp0 + b2[0]) * invt;
                float q1 = (lp1 + b2[1]) * invt;
                float q2 = (lp2 + b2[2]) * invt;
                float q3 = (lp3 + b2[3]) * invt;
                float m = fmaxf(fmaxf(q0, q1), fmaxf(q2, q3));
                float e0 = expf(q0 - m), e1 = expf(q1 - m);
                float e2 = expf(q2 - m), e3 = expf(q3 - m);
                float inv = 1.0f / (e0 + e1 + e2 + e3);
                float w0 = e0 * inv, w1 = e1 * inv, w2v = e2 * inv, w3 = e3 * inv;
                const float* ef = eps_floor + hh * 4;
                w0 = fmaxf(w0, fminf(fmaxf(ef[0], 1e-7f), 0.1f));
                w1 = fmaxf(w1, fminf(fmaxf(ef[1], 1e-7f), 0.1f));
                w2v = fmaxf(w2v, fminf(fmaxf(ef[2], 1e-7f), 0.1f));
                w3 = fmaxf(w3, fminf(fmaxf(ef[3], 1e-7f), 0.1f));
                float inv2 = 1.0f / (w0 + w1 + w2v + w3);
                *(float4*)&out[(size_t)rg * 4] =
                    make_float4(w0 * inv2, w1 * inv2, w2v * inv2, w3 * inv2);
            }
        }
    }
}

// ============================================================================
// Launch
// ============================================================================
extern "C" void kernel_launch(void* const* d_in, const int* in_sizes, int n_in,
                              void* d_out, int out_size)
{
    const float* hidden = (const float*)d_in[0];
    const float* br0    = (const float*)d_in[1];
    const float* br1    = (const float*)d_in[2];
    const float* br2    = (const float*)d_in[3];
    const float* br3    = (const float*)d_in[4];
    const float* W1     = (const float*)d_in[5];
    const float* b1     = (const float*)d_in[6];
    const float* W2     = (const float*)d_in[7];
    const float* b2     = (const float*)d_in[8];
    const float* eps    = (const float*)d_in[9];
    const float* temp   = (const float*)d_in[10];
    float* out = (float*)d_out;

    cudaFuncSetAttribute(pre_kernel, cudaFuncAttributeMaxDynamicSharedMemorySize,
                         PRE_SMEM_FLOATS * 4);
    cudaFuncSetAttribute(main_kernel, cudaFuncAttributeMaxDynamicSharedMemorySize,
                         SM_FLOATS * 4);

    pre_kernel<<<268, 256, PRE_SMEM_FLOATS * 4>>>(hidden, W1, b1);
    main_kernel<<<148, 512, SM_FLOATS * 4>>>(br0, br1, br2, br3, W1, W2,
                                             b2, eps, temp, out);
}